// round 1
// baseline (speedup 1.0000x reference)
#include <cuda_runtime.h>

// ---------------------------------------------------------------------------
// CrossAttention: B=4, C=256, Cr=32, N=4096 (16^3)
// q = wq@x1, k = wk@x2, v = wv@x2
// attn = softmax(q^T k / sqrt(Cr)); ao = v @ attn^T; proj = wp@ao
// out = InstanceNorm(proj) + x1
// ---------------------------------------------------------------------------

#define Bq   4
#define Cc   256
#define CRr  32
#define NSP  4096
#define EPSn 1e-5f

// Scratch (device globals; allocation-free rule)
__device__ __align__(256) float g_q[Bq * CRr * NSP];     // [b][o][n]
__device__ __align__(256) float g_k[Bq * CRr * NSP];     // [b][o][n]
__device__ __align__(256) float g_vT[Bq * NSP * Cc];     // [b][n][c]  (transposed!)
__device__ __align__(256) float g_ao[Bq * Cc * NSP];     // [b][c][n]
__device__ __align__(256) float g_proj[Bq * Cc * NSP];   // [b][c][n]
__device__ __align__(256) float g_wqT[Cc * CRr];         // [c][o]
__device__ __align__(256) float g_wkT[Cc * CRr];
__device__ __align__(256) float g_wvT[Cc * Cc];
__device__ __align__(256) float g_wpT[Cc * Cc];

// ---- packed f32x2 helpers (Blackwell; ptxas won't auto-fuse, must use PTX) ----
__device__ __forceinline__ unsigned long long pack2(float a, float b) {
    unsigned long long r;
    asm("mov.b64 %0, {%1,%2};" : "=l"(r) : "f"(a), "f"(b));
    return r;
}
__device__ __forceinline__ void unpack2(unsigned long long v, float& a, float& b) {
    asm("mov.b64 {%0,%1}, %2;" : "=f"(a), "=f"(b) : "l"(v));
}
__device__ __forceinline__ void fma2(unsigned long long& d, unsigned long long a,
                                     unsigned long long b) {
    asm("fma.rn.f32x2 %0, %1, %2, %0;" : "+l"(d) : "l"(a), "l"(b));
}
__device__ __forceinline__ void mul2(unsigned long long& d, unsigned long long a) {
    asm("mul.rn.f32x2 %0, %0, %1;" : "+l"(d) : "l"(a));
}

// ---------------------------------------------------------------------------
// Kernel 1: weight transpose [o][c] -> [c][o]
// ---------------------------------------------------------------------------
__global__ void transw_kernel(const float* __restrict__ wq, const float* __restrict__ wk,
                              const float* __restrict__ wv, const float* __restrict__ wp) {
    int idx = blockIdx.x * 256 + threadIdx.x;
    if (idx < CRr * Cc) {
        int o = idx / Cc, c = idx % Cc;
        g_wqT[c * CRr + o] = wq[idx];
        g_wkT[c * CRr + o] = wk[idx];
    }
    if (idx < Cc * Cc) {
        int o = idx / Cc, c = idx % Cc;
        g_wvT[c * Cc + o] = wv[idx];
        g_wpT[c * Cc + o] = wp[idx];
    }
}

// ---------------------------------------------------------------------------
// Kernel 2: q/k projection. Each thread owns one n, 32 q-acc + 32 k-acc.
// dyn smem: wqs[Cc][CRr] + wks[Cc][CRr] = 64 KB
// ---------------------------------------------------------------------------
__global__ void __launch_bounds__(128) qk_kernel(const float* __restrict__ x1,
                                                 const float* __restrict__ x2) {
    extern __shared__ float sm[];
    float* wqs = sm;                 // [c][o]
    float* wks = sm + Cc * CRr;

    const int t = threadIdx.x;
    const int b = blockIdx.y;
    const int n = blockIdx.x * 128 + t;

    for (int idx = t; idx < Cc * CRr / 4; idx += 128) {
        ((float4*)wqs)[idx] = ((const float4*)g_wqT)[idx];
        ((float4*)wks)[idx] = ((const float4*)g_wkT)[idx];
    }
    __syncthreads();

    float qa[CRr], ka[CRr];
#pragma unroll
    for (int o = 0; o < CRr; ++o) { qa[o] = 0.f; ka[o] = 0.f; }

    const float* x1p = x1 + (size_t)b * Cc * NSP + n;
    const float* x2p = x2 + (size_t)b * Cc * NSP + n;

#pragma unroll 4
    for (int c = 0; c < Cc; ++c) {
        float xv1 = x1p[(size_t)c * NSP];
        float xv2 = x2p[(size_t)c * NSP];
        const float4* q4 = (const float4*)(wqs + c * CRr);
        const float4* k4 = (const float4*)(wks + c * CRr);
#pragma unroll
        for (int g = 0; g < 8; ++g) {
            float4 wq4 = q4[g];
            qa[4 * g + 0] += xv1 * wq4.x; qa[4 * g + 1] += xv1 * wq4.y;
            qa[4 * g + 2] += xv1 * wq4.z; qa[4 * g + 3] += xv1 * wq4.w;
            float4 wk4 = k4[g];
            ka[4 * g + 0] += xv2 * wk4.x; ka[4 * g + 1] += xv2 * wk4.y;
            ka[4 * g + 2] += xv2 * wk4.z; ka[4 * g + 3] += xv2 * wk4.w;
        }
    }
#pragma unroll
    for (int o = 0; o < CRr; ++o) {
        g_q[((size_t)b * CRr + o) * NSP + n] = qa[o];
        g_k[((size_t)b * CRr + o) * NSP + n] = ka[o];
    }
}

// ---------------------------------------------------------------------------
// Kernel 3: channel GEMM (used for v and for wp-proj).
// mode 0: in = x2 (param),  w = g_wvT, out = g_vT  [b][n][c] (transposed)
// mode 1: in = g_ao,        w = g_wpT, out = g_proj [b][o][n]
// Each thread owns one n and 64 outputs as 32 f32x2 pairs.
// dyn smem: wst[Cc][64] = 64 KB
// ---------------------------------------------------------------------------
__global__ void __launch_bounds__(128) chanmm_kernel(const float* __restrict__ xin, int mode) {
    extern __shared__ float sm[];
    const int t = threadIdx.x;
    const int b = blockIdx.z;
    const int och = blockIdx.y * 64;
    const int n = blockIdx.x * 128 + t;

    const float* in = (mode == 0) ? xin : g_ao;
    const float* wT = (mode == 0) ? g_wvT : g_wpT;

    for (int idx = t; idx < Cc * 16; idx += 128) {      // Cc*64/4 float4s
        int c = idx >> 4, o4 = idx & 15;
        ((float4*)sm)[idx] = ((const float4*)wT)[c * (Cc / 4) + (och >> 2) + o4];
    }
    __syncthreads();

    unsigned long long acc[32];
#pragma unroll
    for (int r = 0; r < 32; ++r) acc[r] = 0ull;

    const float* xp = in + (size_t)b * Cc * NSP + n;
#pragma unroll 4
    for (int c = 0; c < Cc; ++c) {
        float xv = xp[(size_t)c * NSP];
        unsigned long long xx = pack2(xv, xv);
        const ulonglong2* w2 = (const ulonglong2*)(sm + c * 64);
#pragma unroll
        for (int g = 0; g < 16; ++g) {
            ulonglong2 u = w2[g];
            fma2(acc[2 * g], xx, u.x);
            fma2(acc[2 * g + 1], xx, u.y);
        }
    }

    if (mode == 0) {
        float* dst = g_vT + ((size_t)b * NSP + n) * Cc + och;
#pragma unroll
        for (int q = 0; q < 16; ++q) {
            float a0, a1, b0, b1;
            unpack2(acc[2 * q], a0, a1);
            unpack2(acc[2 * q + 1], b0, b1);
            ((float4*)dst)[q] = make_float4(a0, a1, b0, b1);
        }
    } else {
        float* dst = g_proj + ((size_t)b * Cc + och) * NSP + n;
#pragma unroll
        for (int p = 0; p < 32; ++p) {
            float a0, a1;
            unpack2(acc[p], a0, a1);
            dst[(size_t)(2 * p) * NSP] = a0;
            dst[(size_t)(2 * p + 1) * NSP] = a1;
        }
    }
}

// ---------------------------------------------------------------------------
// Kernel 4: flash attention. 64-query tile per CTA, 256 threads.
// smem floats: Qs[32][64]=2048 | Ks[32][64]=2048 | P[64][64]=4096 |
//              Vs[64][256]=16384 | alpha[64] | l[64]  -> 24704 floats = 98816 B
// Thread micro-tile for PV: 4 channels x 16 queries, f32x2 accumulators.
// ---------------------------------------------------------------------------
#define QT 64
#define KT 64
#define FL_SMEM_FLOATS (2048 + 2048 + 4096 + 16384 + 64 + 64)

__global__ void __launch_bounds__(256, 2) flash_kernel() {
    extern __shared__ float sm[];
    float* Qs = sm;                        // [o][i]
    float* Ks = sm + 2048;                 // [o][j]
    float* Pb = sm + 4096;                 // [j][i]
    float* Vs = sm + 8192;                 // [j][c]
    float* alphaS = sm + 24576;            // [i]
    float* lS = sm + 24640;                // [i]

    const int t = threadIdx.x;
    const int b = blockIdx.y;
    const int i0 = blockIdx.x * QT;
    const float scale = 0.17677669529663687f;   // 32^-0.5

    // Load Q tile (pre-scaled)
    for (int idx = t; idx < CRr * QT / 4; idx += 256) {
        int o = idx >> 4, i4 = idx & 15;
        float4 v = *(const float4*)(g_q + ((size_t)b * CRr + o) * NSP + i0 + i4 * 4);
        v.x *= scale; v.y *= scale; v.z *= scale; v.w *= scale;
        *(float4*)(Qs + o * QT + i4 * 4) = v;
    }

    float m_reg = -1e30f, l_reg = 0.0f;    // valid in threads t < 64 (query i = t)

    const int cg = t & 63, ig = t >> 6;
    const int c0 = cg * 4, ibase = ig * 16;
    unsigned long long acc[32];            // O[c0+cc][ibase+2p .. +2p+1]
#pragma unroll
    for (int r = 0; r < 32; ++r) acc[r] = 0ull;

    const int si = (t & 15) * 4;           // S micro-tile: 4i x 4j
    const int sj = (t >> 4) * 4;

    for (int j0 = 0; j0 < NSP; j0 += KT) {
        __syncthreads();                   // prior PV done: Ks/Vs reusable
        for (int idx = t; idx < CRr * KT / 4; idx += 256) {
            int o = idx >> 4, j4 = idx & 15;
            *(float4*)(Ks + o * KT + j4 * 4) =
                *(const float4*)(g_k + ((size_t)b * CRr + o) * NSP + j0 + j4 * 4);
        }
        for (int idx = t; idx < KT * Cc / 4; idx += 256) {
            int j = idx >> 6, c4 = idx & 63;
            *(float4*)(Vs + j * Cc + c4 * 4) =
                *(const float4*)(g_vT + ((size_t)b * NSP + j0 + j) * Cc + c4 * 4);
        }
        __syncthreads();

        // S(i,j) = sum_o Q[o][i] K[o][j], stored at Pb[j][i]
        float s00[4][4];
#pragma unroll
        for (int a = 0; a < 4; ++a)
#pragma unroll
            for (int bb = 0; bb < 4; ++bb) s00[a][bb] = 0.f;
#pragma unroll
        for (int o = 0; o < CRr; ++o) {
            float4 qv = *(const float4*)(Qs + o * QT + si);
            float4 kv = *(const float4*)(Ks + o * KT + sj);
            s00[0][0] += kv.x * qv.x; s00[0][1] += kv.x * qv.y;
            s00[0][2] += kv.x * qv.z; s00[0][3] += kv.x * qv.w;
            s00[1][0] += kv.y * qv.x; s00[1][1] += kv.y * qv.y;
            s00[1][2] += kv.y * qv.z; s00[1][3] += kv.y * qv.w;
            s00[2][0] += kv.z * qv.x; s00[2][1] += kv.z * qv.y;
            s00[2][2] += kv.z * qv.z; s00[2][3] += kv.z * qv.w;
            s00[3][0] += kv.w * qv.x; s00[3][1] += kv.w * qv.y;
            s00[3][2] += kv.w * qv.z; s00[3][3] += kv.w * qv.w;
        }
#pragma unroll
        for (int jj = 0; jj < 4; ++jj)
            *(float4*)(Pb + (sj + jj) * QT + si) =
                make_float4(s00[jj][0], s00[jj][1], s00[jj][2], s00[jj][3]);
        __syncthreads();

        // Online softmax for this tile (threads 0..63, query i = t)
        if (t < QT) {
            float mx = m_reg;
            for (int j = 0; j < KT; ++j) mx = fmaxf(mx, Pb[j * QT + t]);
            float al = __expf(m_reg - mx);
            float sum = 0.f;
            for (int j = 0; j < KT; ++j) {
                float e = __expf(Pb[j * QT + t] - mx);
                Pb[j * QT + t] = e;
                sum += e;
            }
            l_reg = l_reg * al + sum;
            m_reg = mx;
            alphaS[t] = al;
        }
        __syncthreads();

        // Rescale running O by alpha
        {
            const unsigned long long* ap = (const unsigned long long*)(alphaS + ibase);
            unsigned long long a2[8];
#pragma unroll
            for (int p = 0; p < 8; ++p) a2[p] = ap[p];
#pragma unroll
            for (int ccx = 0; ccx < 4; ++ccx)
#pragma unroll
                for (int p = 0; p < 8; ++p) mul2(acc[ccx * 8 + p], a2[p]);
        }

        // PV accumulate: O[c][i] += V[j][c] * P[j][i]
#pragma unroll 2
        for (int j = 0; j < KT; ++j) {
            float4 v4 = *(const float4*)(Vs + j * Cc + c0);
            unsigned long long vv0 = pack2(v4.x, v4.x);
            unsigned long long vv1 = pack2(v4.y, v4.y);
            unsigned long long vv2 = pack2(v4.z, v4.z);
            unsigned long long vv3 = pack2(v4.w, v4.w);
            const ulonglong2* pr2 = (const ulonglong2*)(Pb + j * QT + ibase);
            unsigned long long pr[8];
#pragma unroll
            for (int g = 0; g < 4; ++g) {
                ulonglong2 u = pr2[g];
                pr[2 * g] = u.x; pr[2 * g + 1] = u.y;
            }
#pragma unroll
            for (int p = 0; p < 8; ++p) fma2(acc[0 * 8 + p], vv0, pr[p]);
#pragma unroll
            for (int p = 0; p < 8; ++p) fma2(acc[1 * 8 + p], vv1, pr[p]);
#pragma unroll
            for (int p = 0; p < 8; ++p) fma2(acc[2 * 8 + p], vv2, pr[p]);
#pragma unroll
            for (int p = 0; p < 8; ++p) fma2(acc[3 * 8 + p], vv3, pr[p]);
        }
    }

    __syncthreads();
    if (t < QT) lS[t] = 1.0f / l_reg;
    __syncthreads();

    {
        const unsigned long long* lp = (const unsigned long long*)(lS + ibase);
        unsigned long long l2[8];
#pragma unroll
        for (int p = 0; p < 8; ++p) l2[p] = lp[p];
#pragma unroll
        for (int ccx = 0; ccx < 4; ++ccx) {
            float ov[16];
#pragma unroll
            for (int p = 0; p < 8; ++p) {
                mul2(acc[ccx * 8 + p], l2[p]);
                unpack2(acc[ccx * 8 + p], ov[2 * p], ov[2 * p + 1]);
            }
            float* dst = g_ao + ((size_t)b * Cc + c0 + ccx) * NSP + i0 + ibase;
#pragma unroll
            for (int q4 = 0; q4 < 4; ++q4)
                *(float4*)(dst + q4 * 4) =
                    make_float4(ov[4 * q4], ov[4 * q4 + 1], ov[4 * q4 + 2], ov[4 * q4 + 3]);
        }
    }
}

// ---------------------------------------------------------------------------
// Kernel 5: InstanceNorm (no affine, biased var) + residual, fused output
// ---------------------------------------------------------------------------
__global__ void __launch_bounds__(256) norm_kernel(const float* __restrict__ x1,
                                                   float* __restrict__ out) {
    __shared__ float rs_[8], rs2_[8], mv[2];
    const int bc = blockIdx.x, t = threadIdx.x;
    const float* pr = g_proj + (size_t)bc * NSP;
    const float* xr = x1 + (size_t)bc * NSP;

    float v[16], s = 0.f, s2 = 0.f;
#pragma unroll
    for (int r = 0; r < 16; ++r) {
        v[r] = pr[t + r * 256];
        s += v[r];
        s2 += v[r] * v[r];
    }
#pragma unroll
    for (int o = 16; o > 0; o >>= 1) {
        s += __shfl_down_sync(0xffffffffu, s, o);
        s2 += __shfl_down_sync(0xffffffffu, s2, o);
    }
    if ((t & 31) == 0) { rs_[t >> 5] = s; rs2_[t >> 5] = s2; }
    __syncthreads();
    if (t == 0) {
        float a = 0.f, b2 = 0.f;
        for (int w = 0; w < 8; ++w) { a += rs_[w]; b2 += rs2_[w]; }
        float mean = a / (float)NSP;
        float var = b2 / (float)NSP - mean * mean;
        mv[0] = mean;
        mv[1] = rsqrtf(var + EPSn);
    }
    __syncthreads();
    const float mean = mv[0], rstd = mv[1];
    float* op = out + (size_t)bc * NSP;
#pragma unroll
    for (int r = 0; r < 16; ++r)
        op[t + r * 256] = (v[r] - mean) * rstd + xr[t + r * 256];
}

// ---------------------------------------------------------------------------
extern "C" void kernel_launch(void* const* d_in, const int* in_sizes, int n_in,
                              void* d_out, int out_size) {
    const float* x1 = (const float*)d_in[0];
    const float* x2 = (const float*)d_in[1];
    const float* wq = (const float*)d_in[2];
    const float* wk = (const float*)d_in[3];
    const float* wv = (const float*)d_in[4];
    const float* wp = (const float*)d_in[5];
    float* out = (float*)d_out;

    cudaFuncSetAttribute(qk_kernel, cudaFuncAttributeMaxDynamicSharedMemorySize, 65536);
    cudaFuncSetAttribute(chanmm_kernel, cudaFuncAttributeMaxDynamicSharedMemorySize, 65536);
    cudaFuncSetAttribute(flash_kernel, cudaFuncAttributeMaxDynamicSharedMemorySize,
                         FL_SMEM_FLOATS * (int)sizeof(float));

    transw_kernel<<<Cc * Cc / 256, 256>>>(wq, wk, wv, wp);

    qk_kernel<<<dim3(NSP / 128, Bq), 128, 2 * Cc * CRr * sizeof(float)>>>(x1, x2);

    chanmm_kernel<<<dim3(NSP / 128, Cc / 64, Bq), 128, Cc * 64 * sizeof(float)>>>(x2, 0);

    flash_kernel<<<dim3(NSP / QT, Bq), 256, FL_SMEM_FLOATS * sizeof(float)>>>();

    chanmm_kernel<<<dim3(NSP / 128, Cc / 64, Bq), 128, Cc * 64 * sizeof(float)>>>(nullptr, 1);

    norm_kernel<<<Bq * Cc, 256>>>(x1, out);
}

// round 6
// speedup vs baseline: 1.9452x; 1.9452x over previous
#include <cuda_runtime.h>
#include <cuda_bf16.h>
#include <cstdint>

// ---------------------------------------------------------------------------
// CrossAttention: B=4, C=256, Cr=32, N=4096 (16^3)
// Round 6 (HMMA flash resubmit #2; prior two benches died to broker infra,
// identical source previously demonstrated nondeterministic broker outcomes).
// Change vs round 5: atomic-free l-reduction (per-warp-column partials).
// ---------------------------------------------------------------------------

#define Bq   4
#define Cc   256
#define CRr  32
#define NSP  4096
#define EPSn 1e-5f

// ------------------------------ scratch ------------------------------------
__device__ __align__(256) uint4  g_qT[Bq * NSP * 8];     // [b][n][128B]: 32 bf16 hi | 32 bf16 lo (q pre-scaled)
__device__ __align__(256) uint4  g_kT[Bq * NSP * 8];     // same layout for k
__device__ __align__(256) __nv_bfloat16 g_vh[Bq * Cc * NSP]; // [b][c][n] hi
__device__ __align__(256) __nv_bfloat16 g_vl[Bq * Cc * NSP]; // [b][c][n] lo
__device__ __align__(256) float g_ao[Bq * Cc * NSP];     // [b][c][n]
__device__ __align__(256) float g_proj[Bq * Cc * NSP];   // [b][c][n]
__device__ __align__(256) float g_wqT[Cc * CRr];         // [c][o]
__device__ __align__(256) float g_wkT[Cc * CRr];
__device__ __align__(256) float g_wvT[Cc * Cc];
__device__ __align__(256) float g_wpT[Cc * Cc];

// --------------------------- helpers ---------------------------------------
__device__ __forceinline__ uint32_t smem_to_u32(const void* p) {
    uint32_t a;
    asm("{ .reg .u64 t; cvta.to.shared.u64 t, %1; cvt.u32.u64 %0, t; }" : "=r"(a) : "l"(p));
    return a;
}
__device__ __forceinline__ uint32_t pack_bf2(__nv_bfloat16 a, __nv_bfloat16 b) {
    __nv_bfloat162 p; p.x = a; p.y = b;
    return *reinterpret_cast<uint32_t*>(&p);
}
__device__ __forceinline__ unsigned long long pack2(float a, float b) {
    unsigned long long r;
    asm("mov.b64 %0, {%1,%2};" : "=l"(r) : "f"(a), "f"(b));
    return r;
}
__device__ __forceinline__ void unpack2(unsigned long long v, float& a, float& b) {
    asm("mov.b64 {%0,%1}, %2;" : "=f"(a), "=f"(b) : "l"(v));
}
__device__ __forceinline__ void fma2(unsigned long long& d, unsigned long long a,
                                     unsigned long long b) {
    asm("fma.rn.f32x2 %0, %1, %2, %0;" : "+l"(d) : "l"(a), "l"(b));
}

__device__ __forceinline__ void ldsm_x4(uint32_t& r0, uint32_t& r1, uint32_t& r2,
                                        uint32_t& r3, uint32_t addr) {
    asm volatile("ldmatrix.sync.aligned.m8n8.x4.shared.b16 {%0,%1,%2,%3}, [%4];"
                 : "=r"(r0), "=r"(r1), "=r"(r2), "=r"(r3) : "r"(addr));
}
__device__ __forceinline__ void mma16816(float c[4], const uint32_t a[4],
                                         uint32_t b0, uint32_t b1) {
    asm volatile("mma.sync.aligned.m16n8k16.row.col.f32.bf16.bf16.f32 "
                 "{%0,%1,%2,%3}, {%4,%5,%6,%7}, {%8,%9}, {%0,%1,%2,%3};"
                 : "+f"(c[0]), "+f"(c[1]), "+f"(c[2]), "+f"(c[3])
                 : "r"(a[0]), "r"(a[1]), "r"(a[2]), "r"(a[3]), "r"(b0), "r"(b1));
}

// A-fragment lane address (row-major [row][128B] tile, SW128 swizzle):
// tiles: (rows r0..r0+7, colb) (rows+8, colb) (rows, colb+16) (rows+8, colb+16)
__device__ __forceinline__ uint32_t addrA(uint32_t base, int r0b, int colb, int L) {
    int row = r0b + ((L >> 3) & 1) * 8 + (L & 7);
    int col = colb + (L >> 4) * 16;
    return base + row * 128 + (col ^ ((row & 7) << 4));
}
// B-fragment lane address for two n-tiles (rows = n dim, cols = k dim):
// tiles: (n0..n0+7, colb) (n0.., colb+16) (n0+8.., colb) (n0+8.., colb+16)
__device__ __forceinline__ uint32_t addrB(uint32_t base, int n0, int colb, int L) {
    int row = n0 + (L >> 4) * 8 + (L & 7);
    int col = colb + ((L >> 3) & 1) * 16;
    return base + row * 128 + (col ^ ((row & 7) << 4));
}

// ---------------------------------------------------------------------------
// Kernel 1: weight transpose [o][c] -> [c][o]
// ---------------------------------------------------------------------------
__global__ void transw_kernel(const float* __restrict__ wq, const float* __restrict__ wk,
                              const float* __restrict__ wv, const float* __restrict__ wp) {
    int idx = blockIdx.x * 256 + threadIdx.x;
    if (idx < CRr * Cc) {
        int o = idx / Cc, c = idx % Cc;
        g_wqT[c * CRr + o] = wq[idx];
        g_wkT[c * CRr + o] = wk[idx];
    }
    if (idx < Cc * Cc) {
        int o = idx / Cc, c = idx % Cc;
        g_wvT[c * Cc + o] = wv[idx];
        g_wpT[c * Cc + o] = wp[idx];
    }
}

// ---------------------------------------------------------------------------
// Kernel 2: q/k projection -> bf16 hi/lo rows (q pre-scaled by Cr^-0.5)
// ---------------------------------------------------------------------------
__global__ void __launch_bounds__(128) qk_kernel(const float* __restrict__ x1,
                                                 const float* __restrict__ x2) {
    extern __shared__ float sm[];
    float* wqs = sm;
    float* wks = sm + Cc * CRr;

    const int t = threadIdx.x;
    const int b = blockIdx.y;
    const int n = blockIdx.x * 128 + t;

    for (int idx = t; idx < Cc * CRr / 4; idx += 128) {
        ((float4*)wqs)[idx] = ((const float4*)g_wqT)[idx];
        ((float4*)wks)[idx] = ((const float4*)g_wkT)[idx];
    }
    __syncthreads();

    float qa[CRr], ka[CRr];
#pragma unroll
    for (int o = 0; o < CRr; ++o) { qa[o] = 0.f; ka[o] = 0.f; }

    const float* x1p = x1 + (size_t)b * Cc * NSP + n;
    const float* x2p = x2 + (size_t)b * Cc * NSP + n;

#pragma unroll 4
    for (int c = 0; c < Cc; ++c) {
        float xv1 = x1p[(size_t)c * NSP];
        float xv2 = x2p[(size_t)c * NSP];
        const float4* q4 = (const float4*)(wqs + c * CRr);
        const float4* k4 = (const float4*)(wks + c * CRr);
#pragma unroll
        for (int g = 0; g < 8; ++g) {
            float4 wq4 = q4[g];
            qa[4 * g + 0] += xv1 * wq4.x; qa[4 * g + 1] += xv1 * wq4.y;
            qa[4 * g + 2] += xv1 * wq4.z; qa[4 * g + 3] += xv1 * wq4.w;
            float4 wk4 = k4[g];
            ka[4 * g + 0] += xv2 * wk4.x; ka[4 * g + 1] += xv2 * wk4.y;
            ka[4 * g + 2] += xv2 * wk4.z; ka[4 * g + 3] += xv2 * wk4.w;
        }
    }

    const float qscale = 0.17677669529663687f;   // 32^-0.5
    uint32_t w[32];
#pragma unroll
    for (int p = 0; p < 16; ++p) {
        float a0 = qa[2 * p] * qscale, a1 = qa[2 * p + 1] * qscale;
        __nv_bfloat16 h0 = __float2bfloat16(a0), h1 = __float2bfloat16(a1);
        w[p] = pack_bf2(h0, h1);
        w[16 + p] = pack_bf2(__float2bfloat16(a0 - __bfloat162float(h0)),
                             __float2bfloat16(a1 - __bfloat162float(h1)));
    }
    uint4* dq = g_qT + (size_t)(b * NSP + n) * 8;
#pragma unroll
    for (int c = 0; c < 8; ++c)
        dq[c] = make_uint4(w[4 * c], w[4 * c + 1], w[4 * c + 2], w[4 * c + 3]);

#pragma unroll
    for (int p = 0; p < 16; ++p) {
        float a0 = ka[2 * p], a1 = ka[2 * p + 1];
        __nv_bfloat16 h0 = __float2bfloat16(a0), h1 = __float2bfloat16(a1);
        w[p] = pack_bf2(h0, h1);
        w[16 + p] = pack_bf2(__float2bfloat16(a0 - __bfloat162float(h0)),
                             __float2bfloat16(a1 - __bfloat162float(h1)));
    }
    uint4* dk = g_kT + (size_t)(b * NSP + n) * 8;
#pragma unroll
    for (int c = 0; c < 8; ++c)
        dk[c] = make_uint4(w[4 * c], w[4 * c + 1], w[4 * c + 2], w[4 * c + 3]);
}

// ---------------------------------------------------------------------------
// Kernel 3: channel GEMM.
// mode 0: in = x2, w = g_wvT -> g_vh/g_vl [b][c][n] bf16 hi/lo
// mode 1: in = g_ao, w = g_wpT -> g_proj [b][o][n] fp32
// ---------------------------------------------------------------------------
__global__ void __launch_bounds__(128) chanmm_kernel(const float* __restrict__ xin, int mode) {
    extern __shared__ float sm[];
    const int t = threadIdx.x;
    const int b = blockIdx.z;
    const int och = blockIdx.y * 64;
    const int n = blockIdx.x * 128 + t;

    const float* in = (mode == 0) ? xin : g_ao;
    const float* wT = (mode == 0) ? g_wvT : g_wpT;

    for (int idx = t; idx < Cc * 16; idx += 128) {
        int c = idx >> 4, o4 = idx & 15;
        ((float4*)sm)[idx] = ((const float4*)wT)[c * (Cc / 4) + (och >> 2) + o4];
    }
    __syncthreads();

    unsigned long long acc[32];
#pragma unroll
    for (int r = 0; r < 32; ++r) acc[r] = 0ull;

    const float* xp = in + (size_t)b * Cc * NSP + n;
#pragma unroll 4
    for (int c = 0; c < Cc; ++c) {
        float xv = xp[(size_t)c * NSP];
        unsigned long long xx = pack2(xv, xv);
        const ulonglong2* w2 = (const ulonglong2*)(sm + c * 64);
#pragma unroll
        for (int g = 0; g < 16; ++g) {
            ulonglong2 u = w2[g];
            fma2(acc[2 * g], xx, u.x);
            fma2(acc[2 * g + 1], xx, u.y);
        }
    }

    if (mode == 0) {
#pragma unroll
        for (int p = 0; p < 32; ++p) {
            float a0, a1;
            unpack2(acc[p], a0, a1);
            size_t base = ((size_t)b * Cc + och + 2 * p) * NSP + n;
            __nv_bfloat16 h0 = __float2bfloat16(a0);
            __nv_bfloat16 h1 = __float2bfloat16(a1);
            g_vh[base] = h0;
            g_vh[base + NSP] = h1;
            g_vl[base] = __float2bfloat16(a0 - __bfloat162float(h0));
            g_vl[base + NSP] = __float2bfloat16(a1 - __bfloat162float(h1));
        }
    } else {
        float* dst = g_proj + ((size_t)b * Cc + och) * NSP + n;
#pragma unroll
        for (int p = 0; p < 32; ++p) {
            float a0, a1;
            unpack2(acc[p], a0, a1);
            dst[(size_t)(2 * p) * NSP] = a0;
            dst[(size_t)(2 * p + 1) * NSP] = a1;
        }
    }
}

// ---------------------------------------------------------------------------
// Kernel 4: HMMA flash attention. 64 queries/CTA, 8 warps (2 q-rows x 4 c-cols),
// 256 threads. KT=64. O accumulated in registers over all tiles (exp is safe
// without max-subtraction: |S| <~ 10); divide by row-sum l at the end.
// SMEM (all row-major 128B rows, SW128-swizzled):
//   Q  [64 q][32hi|32lo bf16]   8KB @ 0
//   K  [64 j][32hi|32lo bf16]   8KB @ 8192
//   Phi[64 q][64 j bf16]        8KB @ 16384
//   Plo[64 q][64 j bf16]        8KB @ 24576
//   Vhi[256 c][64 j bf16]      32KB @ 32768   (reused as f32 staging at end)
//   Vlo[256 c][64 j bf16]      32KB @ 65536
//   lfp[4][64] f32              1KB @ 98304  (per-warp-column l partials)
// ---------------------------------------------------------------------------
#define QT 64
#define OFF_Q  0
#define OFF_K  8192
#define OFF_PH 16384
#define OFF_PL 24576
#define OFF_VH 32768
#define OFF_VL 65536
#define OFF_L  98304
#define FL_SMEM 99328

__global__ void __launch_bounds__(256, 2) flash_hmma_kernel() {
    extern __shared__ char smem[];
    const uint32_t sb = smem_to_u32(smem);
    const int t = threadIdx.x;
    const int wid = t >> 5, lane = t & 31;
    const int quad = lane >> 2, qi = lane & 3;
    const int r = wid >> 2;                 // q-row group: q0 = r*32
    const int cw = wid & 3;                 // c-col group: c0 = cw*64, j-slice cw*16
    const int q0 = r * 32;
    const int c0 = cw * 64;
    const int b = blockIdx.y;
    const int i0 = blockIdx.x * QT;

    // Load Q tile (64 rows x 128B, contiguous in gmem)
    {
        const uint4* src = (const uint4*)((const char*)g_qT + ((size_t)(b * NSP) + i0) * 128);
        for (int idx = t; idx < 512; idx += 256) {
            int row = idx >> 3, ch = idx & 7;
            *(uint4*)(smem + OFF_Q + row * 128 + ((ch * 16) ^ ((row & 7) << 4))) = src[idx];
        }
    }

    float Oa[2][8][4];
#pragma unroll
    for (int mt = 0; mt < 2; ++mt)
#pragma unroll
        for (int nt = 0; nt < 8; ++nt)
#pragma unroll
            for (int e = 0; e < 4; ++e) Oa[mt][nt][e] = 0.f;
    float lac[4] = {0.f, 0.f, 0.f, 0.f};

    const char* vhb = (const char*)g_vh + (size_t)(b * Cc) * NSP * 2;
    const char* vlb = (const char*)g_vl + (size_t)(b * Cc) * NSP * 2;

    for (int tI = 0; tI < 64; ++tI) {
        const int j0 = tI * 64;
        __syncthreads();   // previous tile's PV reads of K/V/P are done

        // K tile: 64 rows x 128B contiguous
        {
            const uint4* src = (const uint4*)((const char*)g_kT + ((size_t)(b * NSP) + j0) * 128);
            for (int idx = t; idx < 512; idx += 256) {
                int row = idx >> 3, ch = idx & 7;
                *(uint4*)(smem + OFF_K + row * 128 + ((ch * 16) ^ ((row & 7) << 4))) = src[idx];
            }
        }
        // V tiles as [c][64 j]: 256 rows x 128B, gmem row stride 8192B
        {
            const char* sh = vhb + (size_t)j0 * 2;
            const char* sl = vlb + (size_t)j0 * 2;
            for (int idx = t; idx < 2048; idx += 256) {
                int row = idx >> 3, ch = idx & 7;
                uint32_t d = row * 128 + ((ch * 16) ^ ((row & 7) << 4));
                size_t s = (size_t)row * (NSP * 2) + ch * 16;
                *(uint4*)(smem + OFF_VH + d) = *(const uint4*)(sh + s);
                *(uint4*)(smem + OFF_VL + d) = *(const uint4*)(sl + s);
            }
        }
        __syncthreads();

        // ---- S phase: warp computes S[q0..q0+31][cw*16..cw*16+15] ----
        float sa[2][2][4];
#pragma unroll
        for (int mt = 0; mt < 2; ++mt)
#pragma unroll
            for (int nt = 0; nt < 2; ++nt)
#pragma unroll
                for (int e = 0; e < 4; ++e) sa[mt][nt][e] = 0.f;

#pragma unroll
        for (int kh = 0; kh < 2; ++kh) {
            const int cbh = kh * 32, cbl = 64 + kh * 32;
            uint32_t kf[8];
            ldsm_x4(kf[0], kf[1], kf[2], kf[3], addrB(sb + OFF_K, cw * 16, cbh, lane));
            ldsm_x4(kf[4], kf[5], kf[6], kf[7], addrB(sb + OFF_K, cw * 16, cbl, lane));
#pragma unroll
            for (int mt = 0; mt < 2; ++mt) {
                uint32_t qh[4], ql[4];
                ldsm_x4(qh[0], qh[1], qh[2], qh[3], addrA(sb + OFF_Q, q0 + mt * 16, cbh, lane));
                ldsm_x4(ql[0], ql[1], ql[2], ql[3], addrA(sb + OFF_Q, q0 + mt * 16, cbl, lane));
                mma16816(sa[mt][0], qh, kf[0], kf[1]);   // hi.hi
                mma16816(sa[mt][1], qh, kf[2], kf[3]);
                mma16816(sa[mt][0], qh, kf[4], kf[5]);   // hi.lo
                mma16816(sa[mt][1], qh, kf[6], kf[7]);
                mma16816(sa[mt][0], ql, kf[0], kf[1]);   // lo.hi
                mma16816(sa[mt][1], ql, kf[2], kf[3]);
            }
        }

        // exp, l accumulate, store P hi/lo to SMEM
#pragma unroll
        for (int mt = 0; mt < 2; ++mt) {
#pragma unroll
            for (int nt = 0; nt < 2; ++nt) {
                float e0 = __expf(sa[mt][nt][0]);
                float e1 = __expf(sa[mt][nt][1]);
                float e2 = __expf(sa[mt][nt][2]);
                float e3 = __expf(sa[mt][nt][3]);
                lac[mt * 2 + 0] += e0 + e1;
                lac[mt * 2 + 1] += e2 + e3;
                const int row = q0 + mt * 16 + quad;
                const int byte0 = (cw * 16 + nt * 8 + 2 * qi) * 2;
                const int sw = (row & 7) << 4;          // same for row and row+8
                __nv_bfloat16 h0 = __float2bfloat16(e0), h1 = __float2bfloat16(e1);
                __nv_bfloat16 h2 = __float2bfloat16(e2), h3 = __float2bfloat16(e3);
                *(uint32_t*)(smem + OFF_PH + row * 128 + (byte0 ^ sw)) = pack_bf2(h0, h1);
                *(uint32_t*)(smem + OFF_PH + (row + 8) * 128 + (byte0 ^ sw)) = pack_bf2(h2, h3);
                *(uint32_t*)(smem + OFF_PL + row * 128 + (byte0 ^ sw)) =
                    pack_bf2(__float2bfloat16(e0 - __bfloat162float(h0)),
                             __float2bfloat16(e1 - __bfloat162float(h1)));
                *(uint32_t*)(smem + OFF_PL + (row + 8) * 128 + (byte0 ^ sw)) =
                    pack_bf2(__float2bfloat16(e2 - __bfloat162float(h2)),
                             __float2bfloat16(e3 - __bfloat162float(h3)));
            }
        }
        __syncthreads();

        // ---- PV phase: O[q0..+31][c0..+63] += P[q][j] * V[j][c] ----
#pragma unroll
        for (int kj = 0; kj < 4; ++kj) {
            const int cb = kj * 32;
            uint32_t ah[2][4], al[2][4];
#pragma unroll
            for (int mt = 0; mt < 2; ++mt) {
                ldsm_x4(ah[mt][0], ah[mt][1], ah[mt][2], ah[mt][3],
                        addrA(sb + OFF_PH, q0 + mt * 16, cb, lane));
                ldsm_x4(al[mt][0], al[mt][1], al[mt][2], al[mt][3],
                        addrA(sb + OFF_PL, q0 + mt * 16, cb, lane));
            }
#pragma unroll
            for (int ntp = 0; ntp < 4; ++ntp) {
                uint32_t bh[4], bl[4];
                ldsm_x4(bh[0], bh[1], bh[2], bh[3], addrB(sb + OFF_VH, c0 + ntp * 16, cb, lane));
                ldsm_x4(bl[0], bl[1], bl[2], bl[3], addrB(sb + OFF_VL, c0 + ntp * 16, cb, lane));
#pragma unroll
                for (int mt = 0; mt < 2; ++mt) {
                    mma16816(Oa[mt][ntp * 2 + 0], ah[mt], bh[0], bh[1]);
                    mma16816(Oa[mt][ntp * 2 + 0], ah[mt], bl[0], bl[1]);
                    mma16816(Oa[mt][ntp * 2 + 0], al[mt], bh[0], bh[1]);
                    mma16816(Oa[mt][ntp * 2 + 1], ah[mt], bh[2], bh[3]);
                    mma16816(Oa[mt][ntp * 2 + 1], ah[mt], bl[2], bl[3]);
                    mma16816(Oa[mt][ntp * 2 + 1], al[mt], bh[2], bh[3]);
                }
            }
        }
    }

    // ---- l reduction: per-row sums, atomic-free ----
    // lanes with qi==0 hold this warp's j-slice row sums after the shfl.
    float* lfp = (float*)(smem + OFF_L);     // [4 cw][64 row]
#pragma unroll
    for (int s = 0; s < 4; ++s) {
        lac[s] += __shfl_xor_sync(0xffffffffu, lac[s], 1);
        lac[s] += __shfl_xor_sync(0xffffffffu, lac[s], 2);
    }
    __syncthreads();
    if (qi == 0) {
        lfp[cw * 64 + q0 + quad]          = lac[0];
        lfp[cw * 64 + q0 + quad + 8]      = lac[1];
        lfp[cw * 64 + q0 + 16 + quad]     = lac[2];
        lfp[cw * 64 + q0 + 16 + quad + 8] = lac[3];
    }
    __syncthreads();
    if (t < QT)
        lfp[t] = 1.0f / (lfp[t] + lfp[64 + t] + lfp[128 + t] + lfp[192 + t]);
    __syncthreads();

    float inv[2][2];
#pragma unroll
    for (int mt = 0; mt < 2; ++mt) {
        inv[mt][0] = lfp[q0 + mt * 16 + quad];
        inv[mt][1] = lfp[q0 + mt * 16 + quad + 8];
    }

    // ---- O writeout: stage 64-channel chunks via SMEM for coalesced stores ----
    float* stg = (float*)(smem + OFF_VH);    // [64 c][64 q]
    for (int ch = 0; ch < 4; ++ch) {
        __syncthreads();
        if (cw == ch) {
#pragma unroll
            for (int mt = 0; mt < 2; ++mt) {
#pragma unroll
                for (int nt = 0; nt < 8; ++nt) {
                    int cl = nt * 8 + 2 * qi;
                    int qrow = q0 + mt * 16 + quad;
                    stg[cl * 64 + qrow]           = Oa[mt][nt][0] * inv[mt][0];
                    stg[(cl + 1) * 64 + qrow]     = Oa[mt][nt][1] * inv[mt][0];
                    stg[cl * 64 + qrow + 8]       = Oa[mt][nt][2] * inv[mt][1];
                    stg[(cl + 1) * 64 + qrow + 8] = Oa[mt][nt][3] * inv[mt][1];
                }
            }
        }
        __syncthreads();
        float* dst = g_ao + ((size_t)b * Cc + ch * 64) * NSP + i0;
        for (int idx = t; idx < 1024; idx += 256) {
            int row = idx >> 4, c4 = idx & 15;
            *(float4*)(dst + (size_t)row * NSP + c4 * 4) = *(const float4*)(stg + row * 64 + c4 * 4);
        }
    }
}

// ---------------------------------------------------------------------------
// Kernel 5: InstanceNorm (no affine, biased var) + residual
// ---------------------------------------------------------------------------
__global__ void __launch_bounds__(256) norm_kernel(const float* __restrict__ x1,
                                                   float* __restrict__ out) {
    __shared__ float rs_[8], rs2_[8], mv[2];
    const int bc = blockIdx.x, t = threadIdx.x;
    const float* pr = g_proj + (size_t)bc * NSP;
    const float* xr = x1 + (size_t)bc * NSP;

    float v[16], s = 0.f, s2 = 0.f;
#pragma unroll
    for (int r = 0; r < 16; ++r) {
        v[r] = pr[t + r * 256];
        s += v[r];
        s2 += v[r] * v[r];
    }
#pragma unroll
    for (int o = 16; o > 0; o >>= 1) {
        s += __shfl_down_sync(0xffffffffu, s, o);
        s2 += __shfl_down_sync(0xffffffffu, s2, o);
    }
    if ((t & 31) == 0) { rs_[t >> 5] = s; rs2_[t >> 5] = s2; }
    __syncthreads();
    if (t == 0) {
        float a = 0.f, b2 = 0.f;
        for (int w = 0; w < 8; ++w) { a += rs_[w]; b2 += rs2_[w]; }
        float mean = a / (float)NSP;
        float var = b2 / (float)NSP - mean * mean;
        mv[0] = mean;
        mv[1] = rsqrtf(var + EPSn);
    }
    __syncthreads();
    const float mean = mv[0], rstd = mv[1];
    float* op = out + (size_t)bc * NSP;
#pragma unroll
    for (int r = 0; r < 16; ++r)
        op[t + r * 256] = (v[r] - mean) * rstd + xr[t + r * 256];
}

// ---------------------------------------------------------------------------
extern "C" void kernel_launch(void* const* d_in, const int* in_sizes, int n_in,
                              void* d_out, int out_size) {
    const float* x1 = (const float*)d_in[0];
    const float* x2 = (const float*)d_in[1];
    const float* wq = (const float*)d_in[2];
    const float* wk = (const float*)d_in[3];
    const float* wv = (const float*)d_in[4];
    const float* wp = (const float*)d_in[5];
    float* out = (float*)d_out;

    cudaFuncSetAttribute(qk_kernel, cudaFuncAttributeMaxDynamicSharedMemorySize, 65536);
    cudaFuncSetAttribute(chanmm_kernel, cudaFuncAttributeMaxDynamicSharedMemorySize, 65536);
    cudaFuncSetAttribute(flash_hmma_kernel, cudaFuncAttributeMaxDynamicSharedMemorySize, FL_SMEM);

    transw_kernel<<<Cc * Cc / 256, 256>>>(wq, wk, wv, wp);

    qk_kernel<<<dim3(NSP / 128, Bq), 128, 2 * Cc * CRr * sizeof(float)>>>(x1, x2);

    chanmm_kernel<<<dim3(NSP / 128, Cc / 64, Bq), 128, Cc * 64 * sizeof(float)>>>(x2, 0);

    flash_hmma_kernel<<<dim3(NSP / QT, Bq), 256, FL_SMEM>>>();

    chanmm_kernel<<<dim3(NSP / 128, Cc / 64, Bq), 128, Cc * 64 * sizeof(float)>>>(nullptr, 1);

    norm_kernel<<<Bq * Cc, 256>>>(x1, out);
}

// round 7
// speedup vs baseline: 2.0520x; 1.0549x over previous
#include <cuda_runtime.h>
#include <cuda_bf16.h>
#include <cstdint>

// ---------------------------------------------------------------------------
// CrossAttention: B=4, C=256, Cr=32, N=4096 (16^3)
// Round 7: HMMA flash with QT=128 (512 thr, 1 CTA/SM), cp.async-pipelined
// K/V loads (V hidden behind S+exp; K double-buffered behind PV).
// ---------------------------------------------------------------------------

#define Bq   4
#define Cc   256
#define CRr  32
#define NSP  4096
#define EPSn 1e-5f

// ------------------------------ scratch ------------------------------------
__device__ __align__(256) uint4  g_qT[Bq * NSP * 8];     // [b][n][128B]: 32 bf16 hi | 32 bf16 lo (q pre-scaled)
__device__ __align__(256) uint4  g_kT[Bq * NSP * 8];     // same layout for k
__device__ __align__(256) __nv_bfloat16 g_vh[Bq * Cc * NSP]; // [b][c][n] hi
__device__ __align__(256) __nv_bfloat16 g_vl[Bq * Cc * NSP]; // [b][c][n] lo
__device__ __align__(256) float g_ao[Bq * Cc * NSP];     // [b][c][n]
__device__ __align__(256) float g_proj[Bq * Cc * NSP];   // [b][c][n]
__device__ __align__(256) float g_wqT[Cc * CRr];         // [c][o]
__device__ __align__(256) float g_wkT[Cc * CRr];
__device__ __align__(256) float g_wvT[Cc * Cc];
__device__ __align__(256) float g_wpT[Cc * Cc];

// --------------------------- helpers ---------------------------------------
__device__ __forceinline__ uint32_t smem_to_u32(const void* p) {
    uint32_t a;
    asm("{ .reg .u64 t; cvta.to.shared.u64 t, %1; cvt.u32.u64 %0, t; }" : "=r"(a) : "l"(p));
    return a;
}
__device__ __forceinline__ uint32_t pack_bf2(__nv_bfloat16 a, __nv_bfloat16 b) {
    __nv_bfloat162 p; p.x = a; p.y = b;
    return *reinterpret_cast<uint32_t*>(&p);
}
__device__ __forceinline__ unsigned long long pack2(float a, float b) {
    unsigned long long r;
    asm("mov.b64 %0, {%1,%2};" : "=l"(r) : "f"(a), "f"(b));
    return r;
}
__device__ __forceinline__ void unpack2(unsigned long long v, float& a, float& b) {
    asm("mov.b64 {%0,%1}, %2;" : "=f"(a), "=f"(b) : "l"(v));
}
__device__ __forceinline__ void fma2(unsigned long long& d, unsigned long long a,
                                     unsigned long long b) {
    asm("fma.rn.f32x2 %0, %1, %2, %0;" : "+l"(d) : "l"(a), "l"(b));
}

__device__ __forceinline__ void ldsm_x4(uint32_t& r0, uint32_t& r1, uint32_t& r2,
                                        uint32_t& r3, uint32_t addr) {
    asm volatile("ldmatrix.sync.aligned.m8n8.x4.shared.b16 {%0,%1,%2,%3}, [%4];"
                 : "=r"(r0), "=r"(r1), "=r"(r2), "=r"(r3) : "r"(addr));
}
__device__ __forceinline__ void mma16816(float c[4], const uint32_t a[4],
                                         uint32_t b0, uint32_t b1) {
    asm volatile("mma.sync.aligned.m16n8k16.row.col.f32.bf16.bf16.f32 "
                 "{%0,%1,%2,%3}, {%4,%5,%6,%7}, {%8,%9}, {%0,%1,%2,%3};"
                 : "+f"(c[0]), "+f"(c[1]), "+f"(c[2]), "+f"(c[3])
                 : "r"(a[0]), "r"(a[1]), "r"(a[2]), "r"(a[3]), "r"(b0), "r"(b1));
}
__device__ __forceinline__ void cp_async16(uint32_t dst, const void* src) {
    asm volatile("cp.async.cg.shared.global [%0], [%1], 16;" :: "r"(dst), "l"(src));
}
#define CP_COMMIT() asm volatile("cp.async.commit_group;" ::: "memory")
#define CP_WAIT(N)  asm volatile("cp.async.wait_group %0;" :: "n"(N) : "memory")

// A-fragment lane address (row-major [row][128B] tile, SW128 swizzle)
__device__ __forceinline__ uint32_t addrA(uint32_t base, int r0b, int colb, int L) {
    int row = r0b + ((L >> 3) & 1) * 8 + (L & 7);
    int col = colb + (L >> 4) * 16;
    return base + row * 128 + (col ^ ((row & 7) << 4));
}
// B-fragment lane address for two n-tiles (rows = n dim, cols = k dim)
__device__ __forceinline__ uint32_t addrB(uint32_t base, int n0, int colb, int L) {
    int row = n0 + (L >> 4) * 8 + (L & 7);
    int col = colb + ((L >> 3) & 1) * 16;
    return base + row * 128 + (col ^ ((row & 7) << 4));
}

// ---------------------------------------------------------------------------
// Kernel 1: weight transpose [o][c] -> [c][o]
// ---------------------------------------------------------------------------
__global__ void transw_kernel(const float* __restrict__ wq, const float* __restrict__ wk,
                              const float* __restrict__ wv, const float* __restrict__ wp) {
    int idx = blockIdx.x * 256 + threadIdx.x;
    if (idx < CRr * Cc) {
        int o = idx / Cc, c = idx % Cc;
        g_wqT[c * CRr + o] = wq[idx];
        g_wkT[c * CRr + o] = wk[idx];
    }
    if (idx < Cc * Cc) {
        int o = idx / Cc, c = idx % Cc;
        g_wvT[c * Cc + o] = wv[idx];
        g_wpT[c * Cc + o] = wp[idx];
    }
}

// ---------------------------------------------------------------------------
// Kernel 2: q/k projection -> bf16 hi/lo rows (q pre-scaled by Cr^-0.5)
// ---------------------------------------------------------------------------
__global__ void __launch_bounds__(128) qk_kernel(const float* __restrict__ x1,
                                                 const float* __restrict__ x2) {
    extern __shared__ float sm[];
    float* wqs = sm;
    float* wks = sm + Cc * CRr;

    const int t = threadIdx.x;
    const int b = blockIdx.y;
    const int n = blockIdx.x * 128 + t;

    for (int idx = t; idx < Cc * CRr / 4; idx += 128) {
        ((float4*)wqs)[idx] = ((const float4*)g_wqT)[idx];
        ((float4*)wks)[idx] = ((const float4*)g_wkT)[idx];
    }
    __syncthreads();

    float qa[CRr], ka[CRr];
#pragma unroll
    for (int o = 0; o < CRr; ++o) { qa[o] = 0.f; ka[o] = 0.f; }

    const float* x1p = x1 + (size_t)b * Cc * NSP + n;
    const float* x2p = x2 + (size_t)b * Cc * NSP + n;

#pragma unroll 4
    for (int c = 0; c < Cc; ++c) {
        float xv1 = x1p[(size_t)c * NSP];
        float xv2 = x2p[(size_t)c * NSP];
        const float4* q4 = (const float4*)(wqs + c * CRr);
        const float4* k4 = (const float4*)(wks + c * CRr);
#pragma unroll
        for (int g = 0; g < 8; ++g) {
            float4 wq4 = q4[g];
            qa[4 * g + 0] += xv1 * wq4.x; qa[4 * g + 1] += xv1 * wq4.y;
            qa[4 * g + 2] += xv1 * wq4.z; qa[4 * g + 3] += xv1 * wq4.w;
            float4 wk4 = k4[g];
            ka[4 * g + 0] += xv2 * wk4.x; ka[4 * g + 1] += xv2 * wk4.y;
            ka[4 * g + 2] += xv2 * wk4.z; ka[4 * g + 3] += xv2 * wk4.w;
        }
    }

    const float qscale = 0.17677669529663687f;   // 32^-0.5
    uint32_t w[32];
#pragma unroll
    for (int p = 0; p < 16; ++p) {
        float a0 = qa[2 * p] * qscale, a1 = qa[2 * p + 1] * qscale;
        __nv_bfloat16 h0 = __float2bfloat16(a0), h1 = __float2bfloat16(a1);
        w[p] = pack_bf2(h0, h1);
        w[16 + p] = pack_bf2(__float2bfloat16(a0 - __bfloat162float(h0)),
                             __float2bfloat16(a1 - __bfloat162float(h1)));
    }
    uint4* dq = g_qT + (size_t)(b * NSP + n) * 8;
#pragma unroll
    for (int c = 0; c < 8; ++c)
        dq[c] = make_uint4(w[4 * c], w[4 * c + 1], w[4 * c + 2], w[4 * c + 3]);

#pragma unroll
    for (int p = 0; p < 16; ++p) {
        float a0 = ka[2 * p], a1 = ka[2 * p + 1];
        __nv_bfloat16 h0 = __float2bfloat16(a0), h1 = __float2bfloat16(a1);
        w[p] = pack_bf2(h0, h1);
        w[16 + p] = pack_bf2(__float2bfloat16(a0 - __bfloat162float(h0)),
                             __float2bfloat16(a1 - __bfloat162float(h1)));
    }
    uint4* dk = g_kT + (size_t)(b * NSP + n) * 8;
#pragma unroll
    for (int c = 0; c < 8; ++c)
        dk[c] = make_uint4(w[4 * c], w[4 * c + 1], w[4 * c + 2], w[4 * c + 3]);
}

// ---------------------------------------------------------------------------
// Kernel 3: channel GEMM.
// mode 0: in = x2, w = g_wvT -> g_vh/g_vl [b][c][n] bf16 hi/lo
// mode 1: in = g_ao, w = g_wpT -> g_proj [b][o][n] fp32
// ---------------------------------------------------------------------------
__global__ void __launch_bounds__(128) chanmm_kernel(const float* __restrict__ xin, int mode) {
    extern __shared__ float sm[];
    const int t = threadIdx.x;
    const int b = blockIdx.z;
    const int och = blockIdx.y * 64;
    const int n = blockIdx.x * 128 + t;

    const float* in = (mode == 0) ? xin : g_ao;
    const float* wT = (mode == 0) ? g_wvT : g_wpT;

    for (int idx = t; idx < Cc * 16; idx += 128) {
        int c = idx >> 4, o4 = idx & 15;
        ((float4*)sm)[idx] = ((const float4*)wT)[c * (Cc / 4) + (och >> 2) + o4];
    }
    __syncthreads();

    unsigned long long acc[32];
#pragma unroll
    for (int r = 0; r < 32; ++r) acc[r] = 0ull;

    const float* xp = in + (size_t)b * Cc * NSP + n;
#pragma unroll 4
    for (int c = 0; c < Cc; ++c) {
        float xv = xp[(size_t)c * NSP];
        unsigned long long xx = pack2(xv, xv);
        const ulonglong2* w2 = (const ulonglong2*)(sm + c * 64);
#pragma unroll
        for (int g = 0; g < 16; ++g) {
            ulonglong2 u = w2[g];
            fma2(acc[2 * g], xx, u.x);
            fma2(acc[2 * g + 1], xx, u.y);
        }
    }

    if (mode == 0) {
#pragma unroll
        for (int p = 0; p < 32; ++p) {
            float a0, a1;
            unpack2(acc[p], a0, a1);
            size_t base = ((size_t)b * Cc + och + 2 * p) * NSP + n;
            __nv_bfloat16 h0 = __float2bfloat16(a0);
            __nv_bfloat16 h1 = __float2bfloat16(a1);
            g_vh[base] = h0;
            g_vh[base + NSP] = h1;
            g_vl[base] = __float2bfloat16(a0 - __bfloat162float(h0));
            g_vl[base + NSP] = __float2bfloat16(a1 - __bfloat162float(h1));
        }
    } else {
        float* dst = g_proj + ((size_t)b * Cc + och) * NSP + n;
#pragma unroll
        for (int p = 0; p < 32; ++p) {
            float a0, a1;
            unpack2(acc[p], a0, a1);
            dst[(size_t)(2 * p) * NSP] = a0;
            dst[(size_t)(2 * p + 1) * NSP] = a1;
        }
    }
}

// ---------------------------------------------------------------------------
// Kernel 4: HMMA flash attention. 128 queries/CTA, 16 warps (4 q x 4 c), 512
// threads, 1 CTA/SM. cp.async pipeline: V load hidden behind S+exp; K
// double-buffered, prefetched behind PV. O in registers all 64 tiles.
// SMEM:
//   Q  [128 q][32hi|32lo bf16] 16KB @ 0
//   K0 [ 64 j][...]             8KB @ 16384   (double buffer)
//   K1 [ 64 j][...]             8KB @ 24576
//   Phi[128 q][64 j bf16]      16KB @ 32768
//   Plo[128 q][64 j bf16]      16KB @ 49152
//   Vhi[256 c][64 j bf16]      32KB @ 65536   (reused as f32 staging at end)
//   Vlo[256 c][64 j bf16]      32KB @ 98304
//   lfp[4][128] f32             2KB @ 131072
// ---------------------------------------------------------------------------
#define QT 128
#define OFF_Q  0
#define OFF_K0 16384
#define OFF_PH 32768
#define OFF_PL 49152
#define OFF_VH 65536
#define OFF_VL 98304
#define OFF_L  131072
#define FL_SMEM 133120

__global__ void __launch_bounds__(512, 1) flash_hmma_kernel() {
    extern __shared__ char smem[];
    const uint32_t sb = smem_to_u32(smem);
    const int t = threadIdx.x;
    const int wid = t >> 5, lane = t & 31;
    const int quad = lane >> 2, qi = lane & 3;
    const int r = wid >> 2;                 // q-row group: q0 = r*32 (0..3)
    const int cw = wid & 3;                 // c-col group: c0 = cw*64, j-slice cw*16
    const int q0 = r * 32;
    const int c0 = cw * 64;
    const int b = blockIdx.y;
    const int i0 = blockIdx.x * QT;

    // Load Q tile (128 rows x 128B) + K tile 0, regular loads
    {
        const uint4* src = (const uint4*)((const char*)g_qT + ((size_t)(b * NSP) + i0) * 128);
        for (int idx = t; idx < 1024; idx += 512) {
            int row = idx >> 3, ch = idx & 7;
            *(uint4*)(smem + OFF_Q + row * 128 + ((ch * 16) ^ ((row & 7) << 4))) = src[idx];
        }
        const uint4* ks = (const uint4*)((const char*)g_kT + (size_t)(b * NSP) * 128);
        {
            int idx = t;  // 512 elements, 512 threads
            int row = idx >> 3, ch = idx & 7;
            *(uint4*)(smem + OFF_K0 + row * 128 + ((ch * 16) ^ ((row & 7) << 4))) = ks[idx];
        }
    }
    __syncthreads();

    float Oa[2][8][4];
#pragma unroll
    for (int mt = 0; mt < 2; ++mt)
#pragma unroll
        for (int nt = 0; nt < 8; ++nt)
#pragma unroll
            for (int e = 0; e < 4; ++e) Oa[mt][nt][e] = 0.f;
    float lac[4] = {0.f, 0.f, 0.f, 0.f};

    const char* vhb = (const char*)g_vh + (size_t)(b * Cc) * NSP * 2;
    const char* vlb = (const char*)g_vl + (size_t)(b * Cc) * NSP * 2;

    for (int tI = 0; tI < 64; ++tI) {
        const int j0 = tI * 64;
        const uint32_t kcur = sb + OFF_K0 + (uint32_t)(tI & 1) * 8192;

        // ---- issue V_i cp.async (completes during S+exp) ----
        {
            const char* sh = vhb + (size_t)j0 * 2;
            const char* sl = vlb + (size_t)j0 * 2;
            for (int idx = t; idx < 2048; idx += 512) {
                int row = idx >> 3, ch = idx & 7;
                uint32_t d = row * 128 + ((ch * 16) ^ ((row & 7) << 4));
                size_t s = (size_t)row * (NSP * 2) + ch * 16;
                cp_async16(sb + OFF_VH + d, sh + s);
                cp_async16(sb + OFF_VL + d, sl + s);
            }
        }
        CP_COMMIT();   // group: V_i

        // ---- S phase: warp computes S[q0..q0+31][cw*16..cw*16+15] ----
        float sa[2][2][4];
#pragma unroll
        for (int mt = 0; mt < 2; ++mt)
#pragma unroll
            for (int nt = 0; nt < 2; ++nt)
#pragma unroll
                for (int e = 0; e < 4; ++e) sa[mt][nt][e] = 0.f;

#pragma unroll
        for (int kh = 0; kh < 2; ++kh) {
            const int cbh = kh * 32, cbl = 64 + kh * 32;
            uint32_t kf[8];
            ldsm_x4(kf[0], kf[1], kf[2], kf[3], addrB(kcur, cw * 16, cbh, lane));
            ldsm_x4(kf[4], kf[5], kf[6], kf[7], addrB(kcur, cw * 16, cbl, lane));
#pragma unroll
            for (int mt = 0; mt < 2; ++mt) {
                uint32_t qh[4], ql[4];
                ldsm_x4(qh[0], qh[1], qh[2], qh[3], addrA(sb + OFF_Q, q0 + mt * 16, cbh, lane));
                ldsm_x4(ql[0], ql[1], ql[2], ql[3], addrA(sb + OFF_Q, q0 + mt * 16, cbl, lane));
                mma16816(sa[mt][0], qh, kf[0], kf[1]);   // hi.hi
                mma16816(sa[mt][1], qh, kf[2], kf[3]);
                mma16816(sa[mt][0], qh, kf[4], kf[5]);   // hi.lo
                mma16816(sa[mt][1], qh, kf[6], kf[7]);
                mma16816(sa[mt][0], ql, kf[0], kf[1]);   // lo.hi
                mma16816(sa[mt][1], ql, kf[2], kf[3]);
            }
        }

        // exp, l accumulate, store P hi/lo to SMEM
#pragma unroll
        for (int mt = 0; mt < 2; ++mt) {
#pragma unroll
            for (int nt = 0; nt < 2; ++nt) {
                float e0 = __expf(sa[mt][nt][0]);
                float e1 = __expf(sa[mt][nt][1]);
                float e2 = __expf(sa[mt][nt][2]);
                float e3 = __expf(sa[mt][nt][3]);
                lac[mt * 2 + 0] += e0 + e1;
                lac[mt * 2 + 1] += e2 + e3;
                const int row = q0 + mt * 16 + quad;
                const int byte0 = (cw * 16 + nt * 8 + 2 * qi) * 2;
                const int sw = (row & 7) << 4;          // same for row and row+8
                __nv_bfloat16 h0 = __float2bfloat16(e0), h1 = __float2bfloat16(e1);
                __nv_bfloat16 h2 = __float2bfloat16(e2), h3 = __float2bfloat16(e3);
                *(uint32_t*)(smem + OFF_PH + row * 128 + (byte0 ^ sw)) = pack_bf2(h0, h1);
                *(uint32_t*)(smem + OFF_PH + (row + 8) * 128 + (byte0 ^ sw)) = pack_bf2(h2, h3);
                *(uint32_t*)(smem + OFF_PL + row * 128 + (byte0 ^ sw)) =
                    pack_bf2(__float2bfloat16(e0 - __bfloat162float(h0)),
                             __float2bfloat16(e1 - __bfloat162float(h1)));
                *(uint32_t*)(smem + OFF_PL + (row + 8) * 128 + (byte0 ^ sw)) =
                    pack_bf2(__float2bfloat16(e2 - __bfloat162float(h2)),
                             __float2bfloat16(e3 - __bfloat162float(h3)));
            }
        }

        // ---- prefetch K_{i+1} into alternate buffer (hidden behind PV) ----
        {
            const int jn = (tI < 63) ? (j0 + 64) : 0;
            const char* ks = (const char*)g_kT + ((size_t)(b * NSP) + jn) * 128;
            int idx = t;
            int row = idx >> 3, ch = idx & 7;
            uint32_t d = row * 128 + ((ch * 16) ^ ((row & 7) << 4));
            cp_async16(sb + OFF_K0 + (uint32_t)((tI + 1) & 1) * 8192 + d, ks + idx * 16 - (idx * 16 - ((size_t)row * 128 + ch * 16)));
        }
        CP_COMMIT();   // group: K_{i+1}
        CP_WAIT(1);    // V_i landed (K may still be in flight)
        __syncthreads();   // P + V visible to all warps

        // ---- PV phase: O[q0..+31][c0..+63] += P[q][j] * V[j][c] ----
#pragma unroll
        for (int kj = 0; kj < 4; ++kj) {
            const int cb = kj * 32;
            uint32_t ah[2][4], al[2][4];
#pragma unroll
            for (int mt = 0; mt < 2; ++mt) {
                ldsm_x4(ah[mt][0], ah[mt][1], ah[mt][2], ah[mt][3],
                        addrA(sb + OFF_PH, q0 + mt * 16, cb, lane));
                ldsm_x4(al[mt][0], al[mt][1], al[mt][2], al[mt][3],
                        addrA(sb + OFF_PL, q0 + mt * 16, cb, lane));
            }
#pragma unroll
            for (int ntp = 0; ntp < 4; ++ntp) {
                uint32_t bh[4], bl[4];
                ldsm_x4(bh[0], bh[1], bh[2], bh[3], addrB(sb + OFF_VH, c0 + ntp * 16, cb, lane));
                ldsm_x4(bl[0], bl[1], bl[2], bl[3], addrB(sb + OFF_VL, c0 + ntp * 16, cb, lane));
#pragma unroll
                for (int mt = 0; mt < 2; ++mt) {
                    mma16816(Oa[mt][ntp * 2 + 0], ah[mt], bh[0], bh[1]);
                    mma16816(Oa[mt][ntp * 2 + 0], ah[mt], bl[0], bl[1]);
                    mma16816(Oa[mt][ntp * 2 + 0], al[mt], bh[0], bh[1]);
                    mma16816(Oa[mt][ntp * 2 + 1], ah[mt], bh[2], bh[3]);
                    mma16816(Oa[mt][ntp * 2 + 1], ah[mt], bl[2], bl[3]);
                    mma16816(Oa[mt][ntp * 2 + 1], al[mt], bh[2], bh[3]);
                }
            }
        }
        CP_WAIT(0);        // K_{i+1} landed
        __syncthreads();   // all PV reads of V/P done; K visible
    }

    // ---- l reduction: per-row sums, atomic-free ----
    float* lfp = (float*)(smem + OFF_L);     // [4 cw][128 row]
#pragma unroll
    for (int s = 0; s < 4; ++s) {
        lac[s] += __shfl_xor_sync(0xffffffffu, lac[s], 1);
        lac[s] += __shfl_xor_sync(0xffffffffu, lac[s], 2);
    }
    if (qi == 0) {
        lfp[cw * 128 + q0 + quad]          = lac[0];
        lfp[cw * 128 + q0 + quad + 8]      = lac[1];
        lfp[cw * 128 + q0 + 16 + quad]     = lac[2];
        lfp[cw * 128 + q0 + 16 + quad + 8] = lac[3];
    }
    __syncthreads();
    if (t < QT)
        lfp[t] = 1.0f / (lfp[t] + lfp[128 + t] + lfp[256 + t] + lfp[384 + t]);
    __syncthreads();

    float inv[2][2];
#pragma unroll
    for (int mt = 0; mt < 2; ++mt) {
        inv[mt][0] = lfp[q0 + mt * 16 + quad];
        inv[mt][1] = lfp[q0 + mt * 16 + quad + 8];
    }

    // ---- O writeout: stage 64-channel chunks via SMEM for coalesced stores ----
    float* stg = (float*)(smem + OFF_VH);    // [64 c][128 q] f32 = 32KB
    for (int ch = 0; ch < 4; ++ch) {
        __syncthreads();
        if (cw == ch) {
#pragma unroll
            for (int mt = 0; mt < 2; ++mt) {
#pragma unroll
                for (int nt = 0; nt < 8; ++nt) {
                    int cl = nt * 8 + 2 * qi;
                    int qrow = q0 + mt * 16 + quad;
                    stg[cl * 128 + qrow]           = Oa[mt][nt][0] * inv[mt][0];
                    stg[(cl + 1) * 128 + qrow]     = Oa[mt][nt][1] * inv[mt][0];
                    stg[cl * 128 + qrow + 8]       = Oa[mt][nt][2] * inv[mt][1];
                    stg[(cl + 1) * 128 + qrow + 8] = Oa[mt][nt][3] * inv[mt][1];
                }
            }
        }
        __syncthreads();
        float* dst = g_ao + ((size_t)b * Cc + ch * 64) * NSP + i0;
        for (int idx = t; idx < 2048; idx += 512) {
            int row = idx >> 5, c4 = idx & 31;
            *(float4*)(dst + (size_t)row * NSP + c4 * 4) = *(const float4*)(stg + row * 128 + c4 * 4);
        }
    }
}

// ---------------------------------------------------------------------------
// Kernel 5: InstanceNorm (no affine, biased var) + residual
// ---------------------------------------------------------------------------
__global__ void __launch_bounds__(256) norm_kernel(const float* __restrict__ x1,
                                                   float* __restrict__ out) {
    __shared__ float rs_[8], rs2_[8], mv[2];
    const int bc = blockIdx.x, t = threadIdx.x;
    const float* pr = g_proj + (size_t)bc * NSP;
    const float* xr = x1 + (size_t)bc * NSP;

    float v[16], s = 0.f, s2 = 0.f;
#pragma unroll
    for (int r = 0; r < 16; ++r) {
        v[r] = pr[t + r * 256];
        s += v[r];
        s2 += v[r] * v[r];
    }
#pragma unroll
    for (int o = 16; o > 0; o >>= 1) {
        s += __shfl_down_sync(0xffffffffu, s, o);
        s2 += __shfl_down_sync(0xffffffffu, s2, o);
    }
    if ((t & 31) == 0) { rs_[t >> 5] = s; rs2_[t >> 5] = s2; }
    __syncthreads();
    if (t == 0) {
        float a = 0.f, b2 = 0.f;
        for (int w = 0; w < 8; ++w) { a += rs_[w]; b2 += rs2_[w]; }
        float mean = a / (float)NSP;
        float var = b2 / (float)NSP - mean * mean;
        mv[0] = mean;
        mv[1] = rsqrtf(var + EPSn);
    }
    __syncthreads();
    const float mean = mv[0], rstd = mv[1];
    float* op = out + (size_t)bc * NSP;
#pragma unroll
    for (int r = 0; r < 16; ++r)
        op[t + r * 256] = (v[r] - mean) * rstd + xr[t + r * 256];
}

// ---------------------------------------------------------------------------
extern "C" void kernel_launch(void* const* d_in, const int* in_sizes, int n_in,
                              void* d_out, int out_size) {
    const float* x1 = (const float*)d_in[0];
    const float* x2 = (const float*)d_in[1];
    const float* wq = (const float*)d_in[2];
    const float* wk = (const float*)d_in[3];
    const float* wv = (const float*)d_in[4];
    const float* wp = (const float*)d_in[5];
    float* out = (float*)d_out;

    cudaFuncSetAttribute(qk_kernel, cudaFuncAttributeMaxDynamicSharedMemorySize, 65536);
    cudaFuncSetAttribute(chanmm_kernel, cudaFuncAttributeMaxDynamicSharedMemorySize, 65536);
    cudaFuncSetAttribute(flash_hmma_kernel, cudaFuncAttributeMaxDynamicSharedMemorySize, FL_SMEM);

    transw_kernel<<<Cc * Cc / 256, 256>>>(wq, wk, wv, wp);

    qk_kernel<<<dim3(NSP / 128, Bq), 128, 2 * Cc * CRr * sizeof(float)>>>(x1, x2);

    chanmm_kernel<<<dim3(NSP / 128, Cc / 64, Bq), 128, Cc * 64 * sizeof(float)>>>(x2, 0);

    flash_hmma_kernel<<<dim3(NSP / QT, Bq), 512, FL_SMEM>>>();

    chanmm_kernel<<<dim3(NSP / 128, Cc / 64, Bq), 128, Cc * 64 * sizeof(float)>>>(nullptr, 1);

    norm_kernel<<<Bq * Cc, 256>>>(x1, out);
}

// round 11
// speedup vs baseline: 2.1922x; 1.0683x over previous
#include <cuda_runtime.h>
#include <cuda_bf16.h>
#include <cstdint>

// ---------------------------------------------------------------------------
// CrossAttention: B=4, C=256, Cr=32, N=4096 (16^3)
// Round 11: round-7 passing source with ONE contained change: chanmm at
// 256 thr x 32 outputs (more occupancy, fewer regs). Rounds 8-10's new
// kernels (hgemm/split/bf16-transw) are removed entirely -- they carried an
// unattributed 128MiB local-pool growth.
// ---------------------------------------------------------------------------

#define Bq   4
#define Cc   256
#define CRr  32
#define NSP  4096
#define EPSn 1e-5f

// ------------------------------ scratch ------------------------------------
__device__ __align__(256) uint4  g_qT[Bq * NSP * 8];     // [b][n][128B]: 32 bf16 hi | 32 bf16 lo (q pre-scaled)
__device__ __align__(256) uint4  g_kT[Bq * NSP * 8];     // same layout for k
__device__ __align__(256) __nv_bfloat16 g_vh[Bq * Cc * NSP]; // [b][c][n] hi
__device__ __align__(256) __nv_bfloat16 g_vl[Bq * Cc * NSP]; // [b][c][n] lo
__device__ __align__(256) float g_ao[Bq * Cc * NSP];     // [b][c][n]
__device__ __align__(256) float g_proj[Bq * Cc * NSP];   // [b][c][n]
__device__ __align__(256) float g_wqT[Cc * CRr];         // [c][o]
__device__ __align__(256) float g_wkT[Cc * CRr];
__device__ __align__(256) float g_wvT[Cc * Cc];
__device__ __align__(256) float g_wpT[Cc * Cc];

// --------------------------- helpers ---------------------------------------
__device__ __forceinline__ uint32_t smem_to_u32(const void* p) {
    uint32_t a;
    asm("{ .reg .u64 t; cvta.to.shared.u64 t, %1; cvt.u32.u64 %0, t; }" : "=r"(a) : "l"(p));
    return a;
}
__device__ __forceinline__ uint32_t pack_bf2(__nv_bfloat16 a, __nv_bfloat16 b) {
    __nv_bfloat162 p; p.x = a; p.y = b;
    return *reinterpret_cast<uint32_t*>(&p);
}
__device__ __forceinline__ unsigned long long pack2(float a, float b) {
    unsigned long long r;
    asm("mov.b64 %0, {%1,%2};" : "=l"(r) : "f"(a), "f"(b));
    return r;
}
__device__ __forceinline__ void unpack2(unsigned long long v, float& a, float& b) {
    asm("mov.b64 {%0,%1}, %2;" : "=f"(a), "=f"(b) : "l"(v));
}
__device__ __forceinline__ void fma2(unsigned long long& d, unsigned long long a,
                                     unsigned long long b) {
    asm("fma.rn.f32x2 %0, %1, %2, %0;" : "+l"(d) : "l"(a), "l"(b));
}

__device__ __forceinline__ void ldsm_x4(uint32_t& r0, uint32_t& r1, uint32_t& r2,
                                        uint32_t& r3, uint32_t addr) {
    asm volatile("ldmatrix.sync.aligned.m8n8.x4.shared.b16 {%0,%1,%2,%3}, [%4];"
                 : "=r"(r0), "=r"(r1), "=r"(r2), "=r"(r3) : "r"(addr));
}
__device__ __forceinline__ void mma16816(float c[4], const uint32_t a[4],
                                         uint32_t b0, uint32_t b1) {
    asm volatile("mma.sync.aligned.m16n8k16.row.col.f32.bf16.bf16.f32 "
                 "{%0,%1,%2,%3}, {%4,%5,%6,%7}, {%8,%9}, {%0,%1,%2,%3};"
                 : "+f"(c[0]), "+f"(c[1]), "+f"(c[2]), "+f"(c[3])
                 : "r"(a[0]), "r"(a[1]), "r"(a[2]), "r"(a[3]), "r"(b0), "r"(b1));
}
__device__ __forceinline__ void cp_async16(uint32_t dst, const void* src) {
    asm volatile("cp.async.cg.shared.global [%0], [%1], 16;" :: "r"(dst), "l"(src));
}
#define CP_COMMIT() asm volatile("cp.async.commit_group;" ::: "memory")
#define CP_WAIT(N)  asm volatile("cp.async.wait_group %0;" :: "n"(N) : "memory")

// A-fragment lane address (row-major [row][128B] tile, SW128 swizzle)
__device__ __forceinline__ uint32_t addrA(uint32_t base, int r0b, int colb, int L) {
    int row = r0b + ((L >> 3) & 1) * 8 + (L & 7);
    int col = colb + (L >> 4) * 16;
    return base + row * 128 + (col ^ ((row & 7) << 4));
}
// B-fragment lane address for two n-tiles (rows = n dim, cols = k dim)
__device__ __forceinline__ uint32_t addrB(uint32_t base, int n0, int colb, int L) {
    int row = n0 + (L >> 4) * 8 + (L & 7);
    int col = colb + ((L >> 3) & 1) * 16;
    return base + row * 128 + (col ^ ((row & 7) << 4));
}

// ---------------------------------------------------------------------------
// Kernel 1: weight transpose [o][c] -> [c][o]
// ---------------------------------------------------------------------------
__global__ void transw_kernel(const float* __restrict__ wq, const float* __restrict__ wk,
                              const float* __restrict__ wv, const float* __restrict__ wp) {
    int idx = blockIdx.x * 256 + threadIdx.x;
    if (idx < CRr * Cc) {
        int o = idx / Cc, c = idx % Cc;
        g_wqT[c * CRr + o] = wq[idx];
        g_wkT[c * CRr + o] = wk[idx];
    }
    if (idx < Cc * Cc) {
        int o = idx / Cc, c = idx % Cc;
        g_wvT[c * Cc + o] = wv[idx];
        g_wpT[c * Cc + o] = wp[idx];
    }
}

// ---------------------------------------------------------------------------
// Kernel 2: q/k projection -> bf16 hi/lo rows (q pre-scaled by Cr^-0.5)
// ---------------------------------------------------------------------------
__global__ void __launch_bounds__(128) qk_kernel(const float* __restrict__ x1,
                                                 const float* __restrict__ x2) {
    extern __shared__ float sm[];
    float* wqs = sm;
    float* wks = sm + Cc * CRr;

    const int t = threadIdx.x;
    const int b = blockIdx.y;
    const int n = blockIdx.x * 128 + t;

    for (int idx = t; idx < Cc * CRr / 4; idx += 128) {
        ((float4*)wqs)[idx] = ((const float4*)g_wqT)[idx];
        ((float4*)wks)[idx] = ((const float4*)g_wkT)[idx];
    }
    __syncthreads();

    float qa[CRr], ka[CRr];
#pragma unroll
    for (int o = 0; o < CRr; ++o) { qa[o] = 0.f; ka[o] = 0.f; }

    const float* x1p = x1 + (size_t)b * Cc * NSP + n;
    const float* x2p = x2 + (size_t)b * Cc * NSP + n;

#pragma unroll 4
    for (int c = 0; c < Cc; ++c) {
        float xv1 = x1p[(size_t)c * NSP];
        float xv2 = x2p[(size_t)c * NSP];
        const float4* q4 = (const float4*)(wqs + c * CRr);
        const float4* k4 = (const float4*)(wks + c * CRr);
#pragma unroll
        for (int g = 0; g < 8; ++g) {
            float4 wq4 = q4[g];
            qa[4 * g + 0] += xv1 * wq4.x; qa[4 * g + 1] += xv1 * wq4.y;
            qa[4 * g + 2] += xv1 * wq4.z; qa[4 * g + 3] += xv1 * wq4.w;
            float4 wk4 = k4[g];
            ka[4 * g + 0] += xv2 * wk4.x; ka[4 * g + 1] += xv2 * wk4.y;
            ka[4 * g + 2] += xv2 * wk4.z; ka[4 * g + 3] += xv2 * wk4.w;
        }
    }

    const float qscale = 0.17677669529663687f;   // 32^-0.5
    uint32_t w[32];
#pragma unroll
    for (int p = 0; p < 16; ++p) {
        float a0 = qa[2 * p] * qscale, a1 = qa[2 * p + 1] * qscale;
        __nv_bfloat16 h0 = __float2bfloat16(a0), h1 = __float2bfloat16(a1);
        w[p] = pack_bf2(h0, h1);
        w[16 + p] = pack_bf2(__float2bfloat16(a0 - __bfloat162float(h0)),
                             __float2bfloat16(a1 - __bfloat162float(h1)));
    }
    uint4* dq = g_qT + (size_t)(b * NSP + n) * 8;
#pragma unroll
    for (int c = 0; c < 8; ++c)
        dq[c] = make_uint4(w[4 * c], w[4 * c + 1], w[4 * c + 2], w[4 * c + 3]);

#pragma unroll
    for (int p = 0; p < 16; ++p) {
        float a0 = ka[2 * p], a1 = ka[2 * p + 1];
        __nv_bfloat16 h0 = __float2bfloat16(a0), h1 = __float2bfloat16(a1);
        w[p] = pack_bf2(h0, h1);
        w[16 + p] = pack_bf2(__float2bfloat16(a0 - __bfloat162float(h0)),
                             __float2bfloat16(a1 - __bfloat162float(h1)));
    }
    uint4* dk = g_kT + (size_t)(b * NSP + n) * 8;
#pragma unroll
    for (int c = 0; c < 8; ++c)
        dk[c] = make_uint4(w[4 * c], w[4 * c + 1], w[4 * c + 2], w[4 * c + 3]);
}

// ---------------------------------------------------------------------------
// Kernel 3: channel GEMM (f32x2). 256 thr/CTA, each thread owns one n and 32
// outputs (16 u64 acc). CTA tile 256n x 32o, smem weights [256c][32o] = 32KB.
// Same accumulation order per output as round 7 -> bitwise-identical results,
// 2x resident threads for latency hiding.
// mode 0: in = x2, w = g_wvT -> g_vh/g_vl [b][c][n] bf16 hi/lo
// mode 1: in = g_ao, w = g_wpT -> g_proj [b][o][n] fp32
// ---------------------------------------------------------------------------
__global__ void __launch_bounds__(256) chanmm_kernel(const float* __restrict__ xin, int mode) {
    extern __shared__ float sm[];
    const int t = threadIdx.x;
    const int b = blockIdx.z;
    const int och = blockIdx.y * 32;
    const int n = blockIdx.x * 256 + t;

    const float* in = (mode == 0) ? xin : g_ao;
    const float* wT = (mode == 0) ? g_wvT : g_wpT;

    // stage weights: [c][32o], 2048 float4s
    for (int idx = t; idx < Cc * 8; idx += 256) {
        int c = idx >> 3, o4 = idx & 7;
        ((float4*)sm)[idx] = ((const float4*)wT)[c * (Cc / 4) + (och >> 2) + o4];
    }
    __syncthreads();

    unsigned long long acc[16];
#pragma unroll
    for (int r = 0; r < 16; ++r) acc[r] = 0ull;

    const float* xp = in + (size_t)b * Cc * NSP + n;
#pragma unroll 4
    for (int c = 0; c < Cc; ++c) {
        float xv = xp[(size_t)c * NSP];
        unsigned long long xx = pack2(xv, xv);
        const ulonglong2* w2 = (const ulonglong2*)(sm + c * 32);
#pragma unroll
        for (int g = 0; g < 8; ++g) {
            ulonglong2 u = w2[g];
            fma2(acc[2 * g], xx, u.x);
            fma2(acc[2 * g + 1], xx, u.y);
        }
    }

    if (mode == 0) {
#pragma unroll
        for (int p = 0; p < 16; ++p) {
            float a0, a1;
            unpack2(acc[p], a0, a1);
            size_t base = ((size_t)b * Cc + och + 2 * p) * NSP + n;
            __nv_bfloat16 h0 = __float2bfloat16(a0);
            __nv_bfloat16 h1 = __float2bfloat16(a1);
            g_vh[base] = h0;
            g_vh[base + NSP] = h1;
            g_vl[base] = __float2bfloat16(a0 - __bfloat162float(h0));
            g_vl[base + NSP] = __float2bfloat16(a1 - __bfloat162float(h1));
        }
    } else {
        float* dst = g_proj + ((size_t)b * Cc + och) * NSP + n;
#pragma unroll
        for (int p = 0; p < 16; ++p) {
            float a0, a1;
            unpack2(acc[p], a0, a1);
            dst[(size_t)(2 * p) * NSP] = a0;
            dst[(size_t)(2 * p + 1) * NSP] = a1;
        }
    }
}

// ---------------------------------------------------------------------------
// Kernel 4: HMMA flash attention (round-7 version, byte-identical).
// 128 queries/CTA, 16 warps (4 q x 4 c), 512 threads, cp.async pipeline.
// ---------------------------------------------------------------------------
#define QT 128
#define OFF_Q  0
#define OFF_K0 16384
#define OFF_PH 32768
#define OFF_PL 49152
#define OFF_VH 65536
#define OFF_VL 98304
#define OFF_L  131072
#define FL_SMEM 133120

__global__ void __launch_bounds__(512, 1) flash_hmma_kernel() {
    extern __shared__ char smem[];
    const uint32_t sb = smem_to_u32(smem);
    const int t = threadIdx.x;
    const int wid = t >> 5, lane = t & 31;
    const int quad = lane >> 2, qi = lane & 3;
    const int r = wid >> 2;
    const int cw = wid & 3;
    const int q0 = r * 32;
    const int c0 = cw * 64;
    const int b = blockIdx.y;
    const int i0 = blockIdx.x * QT;

    {
        const uint4* src = (const uint4*)((const char*)g_qT + ((size_t)(b * NSP) + i0) * 128);
        for (int idx = t; idx < 1024; idx += 512) {
            int row = idx >> 3, ch = idx & 7;
            *(uint4*)(smem + OFF_Q + row * 128 + ((ch * 16) ^ ((row & 7) << 4))) = src[idx];
        }
        const uint4* ks = (const uint4*)((const char*)g_kT + (size_t)(b * NSP) * 128);
        {
            int idx = t;
            int row = idx >> 3, ch = idx & 7;
            *(uint4*)(smem + OFF_K0 + row * 128 + ((ch * 16) ^ ((row & 7) << 4))) = ks[idx];
        }
    }
    __syncthreads();

    float Oa[2][8][4];
#pragma unroll
    for (int mt = 0; mt < 2; ++mt)
#pragma unroll
        for (int nt = 0; nt < 8; ++nt)
#pragma unroll
            for (int e = 0; e < 4; ++e) Oa[mt][nt][e] = 0.f;
    float lac[4] = {0.f, 0.f, 0.f, 0.f};

    const char* vhb = (const char*)g_vh + (size_t)(b * Cc) * NSP * 2;
    const char* vlb = (const char*)g_vl + (size_t)(b * Cc) * NSP * 2;

    for (int tI = 0; tI < 64; ++tI) {
        const int j0 = tI * 64;
        const uint32_t kcur = sb + OFF_K0 + (uint32_t)(tI & 1) * 8192;

        {
            const char* sh = vhb + (size_t)j0 * 2;
            const char* sl = vlb + (size_t)j0 * 2;
            for (int idx = t; idx < 2048; idx += 512) {
                int row = idx >> 3, ch = idx & 7;
                uint32_t d = row * 128 + ((ch * 16) ^ ((row & 7) << 4));
                size_t s = (size_t)row * (NSP * 2) + ch * 16;
                cp_async16(sb + OFF_VH + d, sh + s);
                cp_async16(sb + OFF_VL + d, sl + s);
            }
        }
        CP_COMMIT();

        float sa[2][2][4];
#pragma unroll
        for (int mt = 0; mt < 2; ++mt)
#pragma unroll
            for (int nt = 0; nt < 2; ++nt)
#pragma unroll
                for (int e = 0; e < 4; ++e) sa[mt][nt][e] = 0.f;

#pragma unroll
        for (int kh = 0; kh < 2; ++kh) {
            const int cbh = kh * 32, cbl = 64 + kh * 32;
            uint32_t kf[8];
            ldsm_x4(kf[0], kf[1], kf[2], kf[3], addrB(kcur, cw * 16, cbh, lane));
            ldsm_x4(kf[4], kf[5], kf[6], kf[7], addrB(kcur, cw * 16, cbl, lane));
#pragma unroll
            for (int mt = 0; mt < 2; ++mt) {
                uint32_t qh[4], ql[4];
                ldsm_x4(qh[0], qh[1], qh[2], qh[3], addrA(sb + OFF_Q, q0 + mt * 16, cbh, lane));
                ldsm_x4(ql[0], ql[1], ql[2], ql[3], addrA(sb + OFF_Q, q0 + mt * 16, cbl, lane));
                mma16816(sa[mt][0], qh, kf[0], kf[1]);
                mma16816(sa[mt][1], qh, kf[2], kf[3]);
                mma16816(sa[mt][0], qh, kf[4], kf[5]);
                mma16816(sa[mt][1], qh, kf[6], kf[7]);
                mma16816(sa[mt][0], ql, kf[0], kf[1]);
                mma16816(sa[mt][1], ql, kf[2], kf[3]);
            }
        }

#pragma unroll
        for (int mt = 0; mt < 2; ++mt) {
#pragma unroll
            for (int nt = 0; nt < 2; ++nt) {
                float e0 = __expf(sa[mt][nt][0]);
                float e1 = __expf(sa[mt][nt][1]);
                float e2 = __expf(sa[mt][nt][2]);
                float e3 = __expf(sa[mt][nt][3]);
                lac[mt * 2 + 0] += e0 + e1;
                lac[mt * 2 + 1] += e2 + e3;
                const int row = q0 + mt * 16 + quad;
                const int byte0 = (cw * 16 + nt * 8 + 2 * qi) * 2;
                const int sw = (row & 7) << 4;
                __nv_bfloat16 h0 = __float2bfloat16(e0), h1 = __float2bfloat16(e1);
                __nv_bfloat16 h2 = __float2bfloat16(e2), h3 = __float2bfloat16(e3);
                *(uint32_t*)(smem + OFF_PH + row * 128 + (byte0 ^ sw)) = pack_bf2(h0, h1);
                *(uint32_t*)(smem + OFF_PH + (row + 8) * 128 + (byte0 ^ sw)) = pack_bf2(h2, h3);
                *(uint32_t*)(smem + OFF_PL + row * 128 + (byte0 ^ sw)) =
                    pack_bf2(__float2bfloat16(e0 - __bfloat162float(h0)),
                             __float2bfloat16(e1 - __bfloat162float(h1)));
                *(uint32_t*)(smem + OFF_PL + (row + 8) * 128 + (byte0 ^ sw)) =
                    pack_bf2(__float2bfloat16(e2 - __bfloat162float(h2)),
                             __float2bfloat16(e3 - __bfloat162float(h3)));
            }
        }

        {
            const int jn = (tI < 63) ? (j0 + 64) : 0;
            const char* ks = (const char*)g_kT + ((size_t)(b * NSP) + jn) * 128;
            int idx = t;
            int row = idx >> 3, ch = idx & 7;
            uint32_t d = row * 128 + ((ch * 16) ^ ((row & 7) << 4));
            cp_async16(sb + OFF_K0 + (uint32_t)((tI + 1) & 1) * 8192 + d, ks + (size_t)idx * 16);
        }
        CP_COMMIT();
        CP_WAIT(1);
        __syncthreads();

#pragma unroll
        for (int kj = 0; kj < 4; ++kj) {
            const int cb = kj * 32;
            uint32_t ah[2][4], al[2][4];
#pragma unroll
            for (int mt = 0; mt < 2; ++mt) {
                ldsm_x4(ah[mt][0], ah[mt][1], ah[mt][2], ah[mt][3],
                        addrA(sb + OFF_PH, q0 + mt * 16, cb, lane));
                ldsm_x4(al[mt][0], al[mt][1], al[mt][2], al[mt][3],
                        addrA(sb + OFF_PL, q0 + mt * 16, cb, lane));
            }
#pragma unroll
            for (int ntp = 0; ntp < 4; ++ntp) {
                uint32_t bh[4], bl[4];
                ldsm_x4(bh[0], bh[1], bh[2], bh[3], addrB(sb + OFF_VH, c0 + ntp * 16, cb, lane));
                ldsm_x4(bl[0], bl[1], bl[2], bl[3], addrB(sb + OFF_VL, c0 + ntp * 16, cb, lane));
#pragma unroll
                for (int mt = 0; mt < 2; ++mt) {
                    mma16816(Oa[mt][ntp * 2 + 0], ah[mt], bh[0], bh[1]);
                    mma16816(Oa[mt][ntp * 2 + 0], ah[mt], bl[0], bl[1]);
                    mma16816(Oa[mt][ntp * 2 + 0], al[mt], bh[0], bh[1]);
                    mma16816(Oa[mt][ntp * 2 + 1], ah[mt], bh[2], bh[3]);
                    mma16816(Oa[mt][ntp * 2 + 1], ah[mt], bl[2], bl[3]);
                    mma16816(Oa[mt][ntp * 2 + 1], al[mt], bh[2], bh[3]);
                }
            }
        }
        CP_WAIT(0);
        __syncthreads();
    }

    // l reduction (atomic-free)
    float* lfp = (float*)(smem + OFF_L);
#pragma unroll
    for (int s = 0; s < 4; ++s) {
        lac[s] += __shfl_xor_sync(0xffffffffu, lac[s], 1);
        lac[s] += __shfl_xor_sync(0xffffffffu, lac[s], 2);
    }
    if (qi == 0) {
        lfp[cw * 128 + q0 + quad]          = lac[0];
        lfp[cw * 128 + q0 + quad + 8]      = lac[1];
        lfp[cw * 128 + q0 + 16 + quad]     = lac[2];
        lfp[cw * 128 + q0 + 16 + quad + 8] = lac[3];
    }
    __syncthreads();
    if (t < QT)
        lfp[t] = 1.0f / (lfp[t] + lfp[128 + t] + lfp[256 + t] + lfp[384 + t]);
    __syncthreads();

    float inv[2][2];
#pragma unroll
    for (int mt = 0; mt < 2; ++mt) {
        inv[mt][0] = lfp[q0 + mt * 16 + quad];
        inv[mt][1] = lfp[q0 + mt * 16 + quad + 8];
    }

    // O writeout: stage [64c][128q] f32, coalesced fp32 stores to g_ao
    float* stg = (float*)(smem + OFF_VH);
    for (int ch = 0; ch < 4; ++ch) {
        __syncthreads();
        if (cw == ch) {
#pragma unroll
            for (int mt = 0; mt < 2; ++mt) {
#pragma unroll
                for (int nt = 0; nt < 8; ++nt) {
                    int cl = nt * 8 + 2 * qi;
                    int qrow = q0 + mt * 16 + quad;
                    stg[cl * 128 + qrow]           = Oa[mt][nt][0] * inv[mt][0];
                    stg[(cl + 1) * 128 + qrow]     = Oa[mt][nt][1] * inv[mt][0];
                    stg[cl * 128 + qrow + 8]       = Oa[mt][nt][2] * inv[mt][1];
                    stg[(cl + 1) * 128 + qrow + 8] = Oa[mt][nt][3] * inv[mt][1];
                }
            }
        }
        __syncthreads();
        float* dst = g_ao + ((size_t)b * Cc + ch * 64) * NSP + i0;
        for (int idx = t; idx < 2048; idx += 512) {
            int row = idx >> 5, c4 = idx & 31;
            *(float4*)(dst + (size_t)row * NSP + c4 * 4) = *(const float4*)(stg + row * 128 + c4 * 4);
        }
    }
}

// ---------------------------------------------------------------------------
// Kernel 5: InstanceNorm (no affine, biased var) + residual
// ---------------------------------------------------------------------------
__global__ void __launch_bounds__(256) norm_kernel(const float* __restrict__ x1,
                                                   float* __restrict__ out) {
    __shared__ float rs_[8], rs2_[8], mv[2];
    const int bc = blockIdx.x, t = threadIdx.x;
    const float* pr = g_proj + (size_t)bc * NSP;
    const float* xr = x1 + (size_t)bc * NSP;

    float v[16], s = 0.f, s2 = 0.f;
#pragma unroll
    for (int r = 0; r < 16; ++r) {
        v[r] = pr[t + r * 256];
        s += v[r];
        s2 += v[r] * v[r];
    }
#pragma unroll
    for (int o = 16; o > 0; o >>= 1) {
        s += __shfl_down_sync(0xffffffffu, s, o);
        s2 += __shfl_down_sync(0xffffffffu, s2, o);
    }
    if ((t & 31) == 0) { rs_[t >> 5] = s; rs2_[t >> 5] = s2; }
    __syncthreads();
    if (t == 0) {
        float a = 0.f, b2 = 0.f;
        for (int w = 0; w < 8; ++w) { a += rs_[w]; b2 += rs2_[w]; }
        float mean = a / (float)NSP;
        float var = b2 / (float)NSP - mean * mean;
        mv[0] = mean;
        mv[1] = rsqrtf(var + EPSn);
    }
    __syncthreads();
    const float mean = mv[0], rstd = mv[1];
    float* op = out + (size_t)bc * NSP;
#pragma unroll
    for (int r = 0; r < 16; ++r)
        op[t + r * 256] = (v[r] - mean) * rstd + xr[t + r * 256];
}

// ---------------------------------------------------------------------------
extern "C" void kernel_launch(void* const* d_in, const int* in_sizes, int n_in,
                              void* d_out, int out_size) {
    const float* x1 = (const float*)d_in[0];
    const float* x2 = (const float*)d_in[1];
    const float* wq = (const float*)d_in[2];
    const float* wk = (const float*)d_in[3];
    const float* wv = (const float*)d_in[4];
    const float* wp = (const float*)d_in[5];
    float* out = (float*)d_out;

    cudaFuncSetAttribute(qk_kernel, cudaFuncAttributeMaxDynamicSharedMemorySize, 65536);
    cudaFuncSetAttribute(chanmm_kernel, cudaFuncAttributeMaxDynamicSharedMemorySize, 65536);
    cudaFuncSetAttribute(flash_hmma_kernel, cudaFuncAttributeMaxDynamicSharedMemorySize, FL_SMEM);

    transw_kernel<<<Cc * Cc / 256, 256>>>(wq, wk, wv, wp);

    qk_kernel<<<dim3(NSP / 128, Bq), 128, 2 * Cc * CRr * sizeof(float)>>>(x1, x2);

    chanmm_kernel<<<dim3(NSP / 256, Cc / 32, Bq), 256, Cc * 32 * sizeof(float)>>>(x2, 0);

    flash_hmma_kernel<<<dim3(NSP / QT, Bq), 512, FL_SMEM>>>();

    chanmm_kernel<<<dim3(NSP / 256, Cc / 32, Bq), 256, Cc * 32 * sizeof(float)>>>(nullptr, 1);

    norm_kernel<<<Bq * Cc, 256>>>(x1, out);
}

// round 17
// speedup vs baseline: 2.2360x; 1.0200x over previous
#include <cuda_runtime.h>
#include <cuda_bf16.h>
#include <cstdint>

// ---------------------------------------------------------------------------
// CrossAttention: B=4, C=256, Cr=32, N=4096 (16^3)
// Round 17: round-11 baseline (628.8us) + isolated safe wins:
//  - qk inner loop on packed fma.rn.f32x2 (construct exonerated by chanmm)
//  - packed cvt.rn.bf16x2.f32 epilogues (qk + flash P-store), residuals via
//    bf16 bit tricks. hgemm/ldmatrix.trans family permanently abandoned
//    (tripped the 128MiB memory guard in 4 independent builds).
// ---------------------------------------------------------------------------

#define Bq   4
#define Cc   256
#define CRr  32
#define NSP  4096
#define EPSn 1e-5f

// ------------------------------ scratch ------------------------------------
__device__ __align__(256) uint4  g_qT[Bq * NSP * 8];     // [b][n][128B]: 32 bf16 hi | 32 bf16 lo (q pre-scaled)
__device__ __align__(256) uint4  g_kT[Bq * NSP * 8];     // same layout for k
__device__ __align__(256) __nv_bfloat16 g_vh[Bq * Cc * NSP]; // [b][c][n] hi
__device__ __align__(256) __nv_bfloat16 g_vl[Bq * Cc * NSP]; // [b][c][n] lo
__device__ __align__(256) float g_ao[Bq * Cc * NSP];     // [b][c][n]
__device__ __align__(256) float g_proj[Bq * Cc * NSP];   // [b][c][n]
__device__ __align__(256) float g_wqT[Cc * CRr];         // [c][o]
__device__ __align__(256) float g_wkT[Cc * CRr];
__device__ __align__(256) float g_wvT[Cc * Cc];
__device__ __align__(256) float g_wpT[Cc * Cc];

// --------------------------- helpers ---------------------------------------
__device__ __forceinline__ uint32_t smem_to_u32(const void* p) {
    uint32_t a;
    asm("{ .reg .u64 t; cvta.to.shared.u64 t, %1; cvt.u32.u64 %0, t; }" : "=r"(a) : "l"(p));
    return a;
}
__device__ __forceinline__ uint32_t pack_bf2(__nv_bfloat16 a, __nv_bfloat16 b) {
    __nv_bfloat162 p; p.x = a; p.y = b;
    return *reinterpret_cast<uint32_t*>(&p);
}
// packed f32 pair -> bf16x2 (lo in low half), RN rounding == __float2bfloat16
__device__ __forceinline__ uint32_t cvt_bf2(float lo, float hi) {
    uint32_t r;
    asm("cvt.rn.bf16x2.f32 %0, %1, %2;" : "=r"(r) : "f"(hi), "f"(lo));
    return r;
}
__device__ __forceinline__ float bf2_lo_f32(uint32_t p) { return __uint_as_float(p << 16); }
__device__ __forceinline__ float bf2_hi_f32(uint32_t p) { return __uint_as_float(p & 0xffff0000u); }

__device__ __forceinline__ unsigned long long pack2(float a, float b) {
    unsigned long long r;
    asm("mov.b64 %0, {%1,%2};" : "=l"(r) : "f"(a), "f"(b));
    return r;
}
__device__ __forceinline__ void unpack2(unsigned long long v, float& a, float& b) {
    asm("mov.b64 {%0,%1}, %2;" : "=f"(a), "=f"(b) : "l"(v));
}
__device__ __forceinline__ void fma2(unsigned long long& d, unsigned long long a,
                                     unsigned long long b) {
    asm("fma.rn.f32x2 %0, %1, %2, %0;" : "+l"(d) : "l"(a), "l"(b));
}

__device__ __forceinline__ void ldsm_x4(uint32_t& r0, uint32_t& r1, uint32_t& r2,
                                        uint32_t& r3, uint32_t addr) {
    asm volatile("ldmatrix.sync.aligned.m8n8.x4.shared.b16 {%0,%1,%2,%3}, [%4];"
                 : "=r"(r0), "=r"(r1), "=r"(r2), "=r"(r3) : "r"(addr));
}
__device__ __forceinline__ void mma16816(float c[4], const uint32_t a[4],
                                         uint32_t b0, uint32_t b1) {
    asm volatile("mma.sync.aligned.m16n8k16.row.col.f32.bf16.bf16.f32 "
                 "{%0,%1,%2,%3}, {%4,%5,%6,%7}, {%8,%9}, {%0,%1,%2,%3};"
                 : "+f"(c[0]), "+f"(c[1]), "+f"(c[2]), "+f"(c[3])
                 : "r"(a[0]), "r"(a[1]), "r"(a[2]), "r"(a[3]), "r"(b0), "r"(b1));
}
__device__ __forceinline__ void cp_async16(uint32_t dst, const void* src) {
    asm volatile("cp.async.cg.shared.global [%0], [%1], 16;" :: "r"(dst), "l"(src));
}
#define CP_COMMIT() asm volatile("cp.async.commit_group;" ::: "memory")
#define CP_WAIT(N)  asm volatile("cp.async.wait_group %0;" :: "n"(N) : "memory")

// A-fragment lane address (row-major [row][128B] tile, SW128 swizzle)
__device__ __forceinline__ uint32_t addrA(uint32_t base, int r0b, int colb, int L) {
    int row = r0b + ((L >> 3) & 1) * 8 + (L & 7);
    int col = colb + (L >> 4) * 16;
    return base + row * 128 + (col ^ ((row & 7) << 4));
}
// B-fragment lane address for two n-tiles (rows = n dim, cols = k dim)
__device__ __forceinline__ uint32_t addrB(uint32_t base, int n0, int colb, int L) {
    int row = n0 + (L >> 4) * 8 + (L & 7);
    int col = colb + ((L >> 3) & 1) * 16;
    return base + row * 128 + (col ^ ((row & 7) << 4));
}

// ---------------------------------------------------------------------------
// Kernel 1: weight transpose [o][c] -> [c][o]
// ---------------------------------------------------------------------------
__global__ void transw_kernel(const float* __restrict__ wq, const float* __restrict__ wk,
                              const float* __restrict__ wv, const float* __restrict__ wp) {
    int idx = blockIdx.x * 256 + threadIdx.x;
    if (idx < CRr * Cc) {
        int o = idx / Cc, c = idx % Cc;
        g_wqT[c * CRr + o] = wq[idx];
        g_wkT[c * CRr + o] = wk[idx];
    }
    if (idx < Cc * Cc) {
        int o = idx / Cc, c = idx % Cc;
        g_wvT[c * Cc + o] = wv[idx];
        g_wpT[c * Cc + o] = wp[idx];
    }
}

// ---------------------------------------------------------------------------
// Kernel 2: q/k projection -> bf16 hi/lo rows (q pre-scaled by Cr^-0.5).
// Inner loop on packed f32x2; epilogue on packed bf16x2 cvt.
// ---------------------------------------------------------------------------
__global__ void __launch_bounds__(128) qk_kernel(const float* __restrict__ x1,
                                                 const float* __restrict__ x2) {
    extern __shared__ float sm[];
    float* wqs = sm;
    float* wks = sm + Cc * CRr;

    const int t = threadIdx.x;
    const int b = blockIdx.y;
    const int n = blockIdx.x * 128 + t;

    for (int idx = t; idx < Cc * CRr / 4; idx += 128) {
        ((float4*)wqs)[idx] = ((const float4*)g_wqT)[idx];
        ((float4*)wks)[idx] = ((const float4*)g_wkT)[idx];
    }
    __syncthreads();

    unsigned long long qa2[16], ka2[16];
#pragma unroll
    for (int p = 0; p < 16; ++p) { qa2[p] = 0ull; ka2[p] = 0ull; }

    const float* x1p = x1 + (size_t)b * Cc * NSP + n;
    const float* x2p = x2 + (size_t)b * Cc * NSP + n;

#pragma unroll 4
    for (int c = 0; c < Cc; ++c) {
        float xv1 = x1p[(size_t)c * NSP];
        float xv2 = x2p[(size_t)c * NSP];
        unsigned long long xx1 = pack2(xv1, xv1);
        unsigned long long xx2 = pack2(xv2, xv2);
        const ulonglong2* q2 = (const ulonglong2*)(wqs + c * CRr);
        const ulonglong2* k2 = (const ulonglong2*)(wks + c * CRr);
#pragma unroll
        for (int g = 0; g < 8; ++g) {
            ulonglong2 uq = q2[g];
            fma2(qa2[2 * g], xx1, uq.x);
            fma2(qa2[2 * g + 1], xx1, uq.y);
            ulonglong2 uk = k2[g];
            fma2(ka2[2 * g], xx2, uk.x);
            fma2(ka2[2 * g + 1], xx2, uk.y);
        }
    }

    const float qscale = 0.17677669529663687f;   // 32^-0.5
    uint32_t w[32];
#pragma unroll
    for (int p = 0; p < 16; ++p) {
        float a0, a1;
        unpack2(qa2[p], a0, a1);
        a0 *= qscale; a1 *= qscale;
        uint32_t h = cvt_bf2(a0, a1);
        w[p] = h;
        w[16 + p] = cvt_bf2(a0 - bf2_lo_f32(h), a1 - bf2_hi_f32(h));
    }
    uint4* dq = g_qT + (size_t)(b * NSP + n) * 8;
#pragma unroll
    for (int c = 0; c < 8; ++c)
        dq[c] = make_uint4(w[4 * c], w[4 * c + 1], w[4 * c + 2], w[4 * c + 3]);

#pragma unroll
    for (int p = 0; p < 16; ++p) {
        float a0, a1;
        unpack2(ka2[p], a0, a1);
        uint32_t h = cvt_bf2(a0, a1);
        w[p] = h;
        w[16 + p] = cvt_bf2(a0 - bf2_lo_f32(h), a1 - bf2_hi_f32(h));
    }
    uint4* dk = g_kT + (size_t)(b * NSP + n) * 8;
#pragma unroll
    for (int c = 0; c < 8; ++c)
        dk[c] = make_uint4(w[4 * c], w[4 * c + 1], w[4 * c + 2], w[4 * c + 3]);
}

// ---------------------------------------------------------------------------
// Kernel 3: channel GEMM (f32x2), round-11 version (passing, 256 thr x 32 out)
// mode 0: in = x2, w = g_wvT -> g_vh/g_vl [b][c][n] bf16 hi/lo
// mode 1: in = g_ao, w = g_wpT -> g_proj [b][o][n] fp32
// ---------------------------------------------------------------------------
__global__ void __launch_bounds__(256) chanmm_kernel(const float* __restrict__ xin, int mode) {
    extern __shared__ float sm[];
    const int t = threadIdx.x;
    const int b = blockIdx.z;
    const int och = blockIdx.y * 32;
    const int n = blockIdx.x * 256 + t;

    const float* in = (mode == 0) ? xin : g_ao;
    const float* wT = (mode == 0) ? g_wvT : g_wpT;

    for (int idx = t; idx < Cc * 8; idx += 256) {
        int c = idx >> 3, o4 = idx & 7;
        ((float4*)sm)[idx] = ((const float4*)wT)[c * (Cc / 4) + (och >> 2) + o4];
    }
    __syncthreads();

    unsigned long long acc[16];
#pragma unroll
    for (int r = 0; r < 16; ++r) acc[r] = 0ull;

    const float* xp = in + (size_t)b * Cc * NSP + n;
#pragma unroll 4
    for (int c = 0; c < Cc; ++c) {
        float xv = xp[(size_t)c * NSP];
        unsigned long long xx = pack2(xv, xv);
        const ulonglong2* w2 = (const ulonglong2*)(sm + c * 32);
#pragma unroll
        for (int g = 0; g < 8; ++g) {
            ulonglong2 u = w2[g];
            fma2(acc[2 * g], xx, u.x);
            fma2(acc[2 * g + 1], xx, u.y);
        }
    }

    if (mode == 0) {
#pragma unroll
        for (int p = 0; p < 16; ++p) {
            float a0, a1;
            unpack2(acc[p], a0, a1);
            size_t base = ((size_t)b * Cc + och + 2 * p) * NSP + n;
            __nv_bfloat16 h0 = __float2bfloat16(a0);
            __nv_bfloat16 h1 = __float2bfloat16(a1);
            g_vh[base] = h0;
            g_vh[base + NSP] = h1;
            g_vl[base] = __float2bfloat16(a0 - __bfloat162float(h0));
            g_vl[base + NSP] = __float2bfloat16(a1 - __bfloat162float(h1));
        }
    } else {
        float* dst = g_proj + ((size_t)b * Cc + och) * NSP + n;
#pragma unroll
        for (int p = 0; p < 16; ++p) {
            float a0, a1;
            unpack2(acc[p], a0, a1);
            dst[(size_t)(2 * p) * NSP] = a0;
            dst[(size_t)(2 * p + 1) * NSP] = a1;
        }
    }
}

// ---------------------------------------------------------------------------
// Kernel 4: HMMA flash attention (round-7/11 body; P-store on packed cvt).
// 128 queries/CTA, 16 warps (4 q x 4 c), 512 threads, cp.async pipeline.
// ---------------------------------------------------------------------------
#define QT 128
#define OFF_Q  0
#define OFF_K0 16384
#define OFF_PH 32768
#define OFF_PL 49152
#define OFF_VH 65536
#define OFF_VL 98304
#define OFF_L  131072
#define FL_SMEM 133120

__global__ void __launch_bounds__(512, 1) flash_hmma_kernel() {
    extern __shared__ char smem[];
    const uint32_t sb = smem_to_u32(smem);
    const int t = threadIdx.x;
    const int wid = t >> 5, lane = t & 31;
    const int quad = lane >> 2, qi = lane & 3;
    const int r = wid >> 2;
    const int cw = wid & 3;
    const int q0 = r * 32;
    const int c0 = cw * 64;
    const int b = blockIdx.y;
    const int i0 = blockIdx.x * QT;

    {
        const uint4* src = (const uint4*)((const char*)g_qT + ((size_t)(b * NSP) + i0) * 128);
        for (int idx = t; idx < 1024; idx += 512) {
            int row = idx >> 3, ch = idx & 7;
            *(uint4*)(smem + OFF_Q + row * 128 + ((ch * 16) ^ ((row & 7) << 4))) = src[idx];
        }
        const uint4* ks = (const uint4*)((const char*)g_kT + (size_t)(b * NSP) * 128);
        {
            int idx = t;
            int row = idx >> 3, ch = idx & 7;
            *(uint4*)(smem + OFF_K0 + row * 128 + ((ch * 16) ^ ((row & 7) << 4))) = ks[idx];
        }
    }
    __syncthreads();

    float Oa[2][8][4];
#pragma unroll
    for (int mt = 0; mt < 2; ++mt)
#pragma unroll
        for (int nt = 0; nt < 8; ++nt)
#pragma unroll
            for (int e = 0; e < 4; ++e) Oa[mt][nt][e] = 0.f;
    float lac[4] = {0.f, 0.f, 0.f, 0.f};

    const char* vhb = (const char*)g_vh + (size_t)(b * Cc) * NSP * 2;
    const char* vlb = (const char*)g_vl + (size_t)(b * Cc) * NSP * 2;

    for (int tI = 0; tI < 64; ++tI) {
        const int j0 = tI * 64;
        const uint32_t kcur = sb + OFF_K0 + (uint32_t)(tI & 1) * 8192;

        {
            const char* sh = vhb + (size_t)j0 * 2;
            const char* sl = vlb + (size_t)j0 * 2;
            for (int idx = t; idx < 2048; idx += 512) {
                int row = idx >> 3, ch = idx & 7;
                uint32_t d = row * 128 + ((ch * 16) ^ ((row & 7) << 4));
                size_t s = (size_t)row * (NSP * 2) + ch * 16;
                cp_async16(sb + OFF_VH + d, sh + s);
                cp_async16(sb + OFF_VL + d, sl + s);
            }
        }
        CP_COMMIT();

        float sa[2][2][4];
#pragma unroll
        for (int mt = 0; mt < 2; ++mt)
#pragma unroll
            for (int nt = 0; nt < 2; ++nt)
#pragma unroll
                for (int e = 0; e < 4; ++e) sa[mt][nt][e] = 0.f;

#pragma unroll
        for (int kh = 0; kh < 2; ++kh) {
            const int cbh = kh * 32, cbl = 64 + kh * 32;
            uint32_t kf[8];
            ldsm_x4(kf[0], kf[1], kf[2], kf[3], addrB(kcur, cw * 16, cbh, lane));
            ldsm_x4(kf[4], kf[5], kf[6], kf[7], addrB(kcur, cw * 16, cbl, lane));
#pragma unroll
            for (int mt = 0; mt < 2; ++mt) {
                uint32_t qh[4], ql[4];
                ldsm_x4(qh[0], qh[1], qh[2], qh[3], addrA(sb + OFF_Q, q0 + mt * 16, cbh, lane));
                ldsm_x4(ql[0], ql[1], ql[2], ql[3], addrA(sb + OFF_Q, q0 + mt * 16, cbl, lane));
                mma16816(sa[mt][0], qh, kf[0], kf[1]);
                mma16816(sa[mt][1], qh, kf[2], kf[3]);
                mma16816(sa[mt][0], qh, kf[4], kf[5]);
                mma16816(sa[mt][1], qh, kf[6], kf[7]);
                mma16816(sa[mt][0], ql, kf[0], kf[1]);
                mma16816(sa[mt][1], ql, kf[2], kf[3]);
            }
        }

        // exp + packed-cvt P hi/lo store
#pragma unroll
        for (int mt = 0; mt < 2; ++mt) {
#pragma unroll
            for (int nt = 0; nt < 2; ++nt) {
                float e0 = __expf(sa[mt][nt][0]);
                float e1 = __expf(sa[mt][nt][1]);
                float e2 = __expf(sa[mt][nt][2]);
                float e3 = __expf(sa[mt][nt][3]);
                lac[mt * 2 + 0] += e0 + e1;
                lac[mt * 2 + 1] += e2 + e3;
                const int row = q0 + mt * 16 + quad;
                const int byte0 = (cw * 16 + nt * 8 + 2 * qi) * 2;
                const int sw = (row & 7) << 4;
                uint32_t hA = cvt_bf2(e0, e1);
                uint32_t hB = cvt_bf2(e2, e3);
                uint32_t lA = cvt_bf2(e0 - bf2_lo_f32(hA), e1 - bf2_hi_f32(hA));
                uint32_t lB = cvt_bf2(e2 - bf2_lo_f32(hB), e3 - bf2_hi_f32(hB));
                *(uint32_t*)(smem + OFF_PH + row * 128 + (byte0 ^ sw)) = hA;
                *(uint32_t*)(smem + OFF_PH + (row + 8) * 128 + (byte0 ^ sw)) = hB;
                *(uint32_t*)(smem + OFF_PL + row * 128 + (byte0 ^ sw)) = lA;
                *(uint32_t*)(smem + OFF_PL + (row + 8) * 128 + (byte0 ^ sw)) = lB;
            }
        }

        {
            const int jn = (tI < 63) ? (j0 + 64) : 0;
            const char* ks = (const char*)g_kT + ((size_t)(b * NSP) + jn) * 128;
            int idx = t;
            int row = idx >> 3, ch = idx & 7;
            uint32_t d = row * 128 + ((ch * 16) ^ ((row & 7) << 4));
            cp_async16(sb + OFF_K0 + (uint32_t)((tI + 1) & 1) * 8192 + d, ks + (size_t)idx * 16);
        }
        CP_COMMIT();
        CP_WAIT(1);
        __syncthreads();

#pragma unroll
        for (int kj = 0; kj < 4; ++kj) {
            const int cb = kj * 32;
            uint32_t ah[2][4], al[2][4];
#pragma unroll
            for (int mt = 0; mt < 2; ++mt) {
                ldsm_x4(ah[mt][0], ah[mt][1], ah[mt][2], ah[mt][3],
                        addrA(sb + OFF_PH, q0 + mt * 16, cb, lane));
                ldsm_x4(al[mt][0], al[mt][1], al[mt][2], al[mt][3],
                        addrA(sb + OFF_PL, q0 + mt * 16, cb, lane));
            }
#pragma unroll
            for (int ntp = 0; ntp < 4; ++ntp) {
                uint32_t bh[4], bl[4];
                ldsm_x4(bh[0], bh[1], bh[2], bh[3], addrB(sb + OFF_VH, c0 + ntp * 16, cb, lane));
                ldsm_x4(bl[0], bl[1], bl[2], bl[3], addrB(sb + OFF_VL, c0 + ntp * 16, cb, lane));
#pragma unroll
                for (int mt = 0; mt < 2; ++mt) {
                    mma16816(Oa[mt][ntp * 2 + 0], ah[mt], bh[0], bh[1]);
                    mma16816(Oa[mt][ntp * 2 + 0], ah[mt], bl[0], bl[1]);
                    mma16816(Oa[mt][ntp * 2 + 0], al[mt], bh[0], bh[1]);
                    mma16816(Oa[mt][ntp * 2 + 1], ah[mt], bh[2], bh[3]);
                    mma16816(Oa[mt][ntp * 2 + 1], ah[mt], bl[2], bl[3]);
                    mma16816(Oa[mt][ntp * 2 + 1], al[mt], bh[2], bh[3]);
                }
            }
        }
        CP_WAIT(0);
        __syncthreads();
    }

    // l reduction (atomic-free)
    float* lfp = (float*)(smem + OFF_L);
#pragma unroll
    for (int s = 0; s < 4; ++s) {
        lac[s] += __shfl_xor_sync(0xffffffffu, lac[s], 1);
        lac[s] += __shfl_xor_sync(0xffffffffu, lac[s], 2);
    }
    if (qi == 0) {
        lfp[cw * 128 + q0 + quad]          = lac[0];
        lfp[cw * 128 + q0 + quad + 8]      = lac[1];
        lfp[cw * 128 + q0 + 16 + quad]     = lac[2];
        lfp[cw * 128 + q0 + 16 + quad + 8] = lac[3];
    }
    __syncthreads();
    if (t < QT)
        lfp[t] = 1.0f / (lfp[t] + lfp[128 + t] + lfp[256 + t] + lfp[384 + t]);
    __syncthreads();

    float inv[2][2];
#pragma unroll
    for (int mt = 0; mt < 2; ++mt) {
        inv[mt][0] = lfp[q0 + mt * 16 + quad];
        inv[mt][1] = lfp[q0 + mt * 16 + quad + 8];
    }

    // O writeout: stage [64c][128q] f32, coalesced fp32 stores to g_ao
    float* stg = (float*)(smem + OFF_VH);
    for (int ch = 0; ch < 4; ++ch) {
        __syncthreads();
        if (cw == ch) {
#pragma unroll
            for (int mt = 0; mt < 2; ++mt) {
#pragma unroll
                for (int nt = 0; nt < 8; ++nt) {
                    int cl = nt * 8 + 2 * qi;
                    int qrow = q0 + mt * 16 + quad;
                    stg[cl * 128 + qrow]           = Oa[mt][nt][0] * inv[mt][0];
                    stg[(cl + 1) * 128 + qrow]     = Oa[mt][nt][1] * inv[mt][0];
                    stg[cl * 128 + qrow + 8]       = Oa[mt][nt][2] * inv[mt][1];
                    stg[(cl + 1) * 128 + qrow + 8] = Oa[mt][nt][3] * inv[mt][1];
                }
            }
        }
        __syncthreads();
        float* dst = g_ao + ((size_t)b * Cc + ch * 64) * NSP + i0;
        for (int idx = t; idx < 2048; idx += 512) {
            int row = idx >> 5, c4 = idx & 31;
            *(float4*)(dst + (size_t)row * NSP + c4 * 4) = *(const float4*)(stg + row * 128 + c4 * 4);
        }
    }
}

// ---------------------------------------------------------------------------
// Kernel 5: InstanceNorm (no affine, biased var) + residual
// ---------------------------------------------------------------------------
__global__ void __launch_bounds__(256) norm_kernel(const float* __restrict__ x1,
                                                   float* __restrict__ out) {
    __shared__ float rs_[8], rs2_[8], mv[2];
    const int bc = blockIdx.x, t = threadIdx.x;
    const float* pr = g_proj + (size_t)bc * NSP;
    const float* xr = x1 + (size_t)bc * NSP;

    float v[16], s = 0.f, s2 = 0.f;
#pragma unroll
    for (int r = 0; r < 16; ++r) {
        v[r] = pr[t + r * 256];
        s += v[r];
        s2 += v[r] * v[r];
    }
#pragma unroll
    for (int o = 16; o > 0; o >>= 1) {
        s += __shfl_down_sync(0xffffffffu, s, o);
        s2 += __shfl_down_sync(0xffffffffu, s2, o);
    }
    if ((t & 31) == 0) { rs_[t >> 5] = s; rs2_[t >> 5] = s2; }
    __syncthreads();
    if (t == 0) {
        float a = 0.f, b2 = 0.f;
        for (int w = 0; w < 8; ++w) { a += rs_[w]; b2 += rs2_[w]; }
        float mean = a / (float)NSP;
        float var = b2 / (float)NSP - mean * mean;
        mv[0] = mean;
        mv[1] = rsqrtf(var + EPSn);
    }
    __syncthreads();
    const float mean = mv[0], rstd = mv[1];
    float* op = out + (size_t)bc * NSP;
#pragma unroll
    for (int r = 0; r < 16; ++r)
        op[t + r * 256] = (v[r] - mean) * rstd + xr[t + r * 256];
}

// ---------------------------------------------------------------------------
extern "C" void kernel_launch(void* const* d_in, const int* in_sizes, int n_in,
                              void* d_out, int out_size) {
    const float* x1 = (const float*)d_in[0];
    const float* x2 = (const float*)d_in[1];
    const float* wq = (const float*)d_in[2];
    const float* wk = (const float*)d_in[3];
    const float* wv = (const float*)d_in[4];
    const float* wp = (const float*)d_in[5];
    float* out = (float*)d_out;

    cudaFuncSetAttribute(qk_kernel, cudaFuncAttributeMaxDynamicSharedMemorySize, 65536);
    cudaFuncSetAttribute(chanmm_kernel, cudaFuncAttributeMaxDynamicSharedMemorySize, 65536);
    cudaFuncSetAttribute(flash_hmma_kernel, cudaFuncAttributeMaxDynamicSharedMemorySize, FL_SMEM);

    transw_kernel<<<Cc * Cc / 256, 256>>>(wq, wk, wv, wp);

    qk_kernel<<<dim3(NSP / 128, Bq), 128, 2 * Cc * CRr * sizeof(float)>>>(x1, x2);

    chanmm_kernel<<<dim3(NSP / 256, Cc / 32, Bq), 256, Cc * 32 * sizeof(float)>>>(x2, 0);

    flash_hmma_kernel<<<dim3(NSP / QT, Bq), 512, FL_SMEM>>>();

    chanmm_kernel<<<dim3(NSP / 256, Cc / 32, Bq), 256, Cc * 32 * sizeof(float)>>>(nullptr, 1);

    norm_kernel<<<Bq * Cc, 256>>>(x1, out);
}